// round 2
// baseline (speedup 1.0000x reference)
#include <cuda_runtime.h>
#include <cuda_bf16.h>
#include <cstdint>
#include <cstddef>

// Problem constants (shapes fixed by the dataset).
#define B_    256
#define DIN_  512
#define H_    1024
#define DOUT_ 512
#define T_    256

#define STAGES 4

// ---------------------------------------------------------------------------
// Device scratch. hs: T+1 slabs of [B, H] split bf16 (hi+lo).
// ---------------------------------------------------------------------------
__device__ __nv_bfloat16 g_hs_hi[(size_t)(T_ + 1) * B_ * H_];
__device__ __nv_bfloat16 g_hs_lo[(size_t)(T_ + 1) * B_ * H_];
__device__ __nv_bfloat16 g_Whi[6 * H_ * H_];   // rows: [w_ih(3H); w_hh(3H)] x H
__device__ __nv_bfloat16 g_Wlo[6 * H_ * H_];
__device__ __nv_bfloat16 g_xhi[B_ * DIN_],  g_xlo[B_ * DIN_];
__device__ __nv_bfloat16 g_w1hi[H_ * DIN_], g_w1lo[H_ * DIN_];
__device__ __nv_bfloat16 g_w2hi[H_ * H_],   g_w2lo[H_ * H_];
__device__ __nv_bfloat16 g_t1hi[B_ * H_],   g_t1lo[B_ * H_];
__device__ __nv_bfloat16 g_owhi[DOUT_ * H_], g_owlo[DOUT_ * H_];

// ---------------------------------------------------------------------------
// Split fp32 -> bf16 hi + lo.
// ---------------------------------------------------------------------------
__global__ void split_kernel(int which, const float* __restrict__ src, int n) {
    int i = blockIdx.x * blockDim.x + threadIdx.x;
    if (i >= n) return;
    __nv_bfloat16 *hi, *lo;
    switch (which) {
        case 0: hi = g_xhi;  lo = g_xlo;  break;
        case 1: hi = g_w1hi; lo = g_w1lo; break;
        case 2: hi = g_w2hi; lo = g_w2lo; break;
        case 3: hi = g_Whi;               lo = g_Wlo;               break;
        case 4: hi = g_Whi + 3 * H_ * H_; lo = g_Wlo + 3 * H_ * H_; break;
        default: hi = g_owhi; lo = g_owlo; break;
    }
    float v = src[i];
    __nv_bfloat16 h = __float2bfloat16(v);
    hi[i] = h;
    lo[i] = __float2bfloat16(v - __bfloat162float(h));
}

// ---------------------------------------------------------------------------
// PTX helpers
// ---------------------------------------------------------------------------
__device__ __forceinline__ void mma_bf16(float* c,
                                         uint32_t a0, uint32_t a1, uint32_t a2, uint32_t a3,
                                         uint32_t b0, uint32_t b1) {
    asm volatile(
        "mma.sync.aligned.m16n8k16.row.col.f32.bf16.bf16.f32 "
        "{%0,%1,%2,%3}, {%4,%5,%6,%7}, {%8,%9}, {%0,%1,%2,%3};\n"
        : "+f"(c[0]), "+f"(c[1]), "+f"(c[2]), "+f"(c[3])
        : "r"(a0), "r"(a1), "r"(a2), "r"(a3), "r"(b0), "r"(b1));
}
__device__ __forceinline__ void cp16(uint32_t dst, const void* src) {
    asm volatile("cp.async.cg.shared.global [%0], [%1], 16;\n" :: "r"(dst), "l"(src));
}
__device__ __forceinline__ void cp_commit() {
    asm volatile("cp.async.commit_group;\n");
}
template <int N>
__device__ __forceinline__ void cp_wait() {
    asm volatile("cp.async.wait_group %0;\n" :: "n"(N));
}

__device__ __forceinline__ float sigm(float x) { return 1.0f / (1.0f + __expf(-x)); }
__device__ __forceinline__ float tanh_fast(float x) {
    float a = fabsf(x);
    float e = __expf(-2.0f * a);
    return copysignf((1.0f - e) / (1.0f + e), x);
}

// ---------------------------------------------------------------------------
// Split-bf16 GEMM with cp.async 4-stage pipeline.
// C[M,N] = A[M,K] @ B[N,K]^T + bias[N]
// BM=128, BN=64, BK=32 (=16 u32); 256 threads (8 warps: 4m x 2n of 32x32).
// Stage layout (u32, row stride 20): Ah[128*20] Al[128*20] Bh[64*20] Bl[64*20]
// ---------------------------------------------------------------------------
#define G_SSZ  (384 * 20)                 // u32 per stage
#define G_SMEM (STAGES * G_SSZ * 4)       // 122880 bytes

__global__ __launch_bounds__(256) void gemm3_kernel(
    int which, const float* __restrict__ bias, float* __restrict__ outf,
    int M, int N, int K, int mode)
{
    extern __shared__ uint32_t smem[];

    const __nv_bfloat16 *Ahi, *Alo, *Bhi, *Blo;
    if (which == 0)      { Ahi = g_xhi;  Alo = g_xlo;  Bhi = g_w1hi; Blo = g_w1lo; }
    else if (which == 1) { Ahi = g_t1hi; Alo = g_t1lo; Bhi = g_w2hi; Blo = g_w2lo; }
    else                 { Ahi = g_hs_hi + (size_t)B_ * H_; Alo = g_hs_lo + (size_t)B_ * H_;
                           Bhi = g_owhi; Blo = g_owlo; }
    const uint32_t* A32h = (const uint32_t*)Ahi;
    const uint32_t* A32l = (const uint32_t*)Alo;
    const uint32_t* B32h = (const uint32_t*)Bhi;
    const uint32_t* B32l = (const uint32_t*)Blo;

    int tid  = threadIdx.x;
    int lane = tid & 31, warp = tid >> 5;
    int g = lane >> 2, t4 = lane & 3;
    int wm = warp >> 1, wn = warp & 1;
    int m0 = blockIdx.y * 128;
    int n0 = blockIdx.x * 64;
    int K2 = K >> 1;
    int NT = K >> 5;                       // K / 32
    uint32_t sbase = (uint32_t)__cvta_generic_to_shared(smem);

    // ---- async tile loader: 4 A-chunks + 2 B-chunks of 16B per thread ----
    auto load_tile = [&](int kt, int stage) {
        if (kt < NT) {
            int kc = kt * 16;
            uint32_t base = sbase + (uint32_t)stage * G_SSZ * 4;
#pragma unroll
            for (int i = 0; i < 4; i++) {          // A: 128 rows x 4 chunks x 2 halves
                int c = tid + i * 256;
                int half = c >> 9, rem = c & 511;
                int row = rem >> 2, ch = rem & 3;
                const uint32_t* src = (half ? A32l : A32h)
                                      + (size_t)(m0 + row) * K2 + kc + ch * 4;
                cp16(base + (uint32_t)(half * 128 * 20 + row * 20 + ch * 4) * 4, src);
            }
#pragma unroll
            for (int i = 0; i < 2; i++) {          // B: 64 rows x 4 chunks x 2 halves
                int c = tid + i * 256;
                int half = c >> 8, rem = c & 255;
                int row = rem >> 2, ch = rem & 3;
                const uint32_t* src = (half ? B32l : B32h)
                                      + (size_t)(n0 + row) * K2 + kc + ch * 4;
                cp16(base + (uint32_t)((256 + half * 64) * 20 + row * 20 + ch * 4) * 4, src);
            }
        }
        cp_commit();
    };

    float acc[2][4][4];
#pragma unroll
    for (int a = 0; a < 2; a++)
#pragma unroll
        for (int b = 0; b < 4; b++)
#pragma unroll
            for (int c = 0; c < 4; c++) acc[a][b][c] = 0.0f;

    for (int i = 0; i < STAGES - 1; i++) load_tile(i, i);

    for (int kt = 0; kt < NT; kt++) {
        cp_wait<STAGES - 2>();
        __syncthreads();
        load_tile(kt + STAGES - 1, (kt + STAGES - 1) & (STAGES - 1));

        const uint32_t* st  = smem + (kt & (STAGES - 1)) * G_SSZ;
        const uint32_t* sAh = st;
        const uint32_t* sAl = st + 128 * 20;
        const uint32_t* sBh = st + 256 * 20;
        const uint32_t* sBl = st + 320 * 20;

#pragma unroll
        for (int kk = 0; kk < 2; kk++) {
            int base = kk * 8 + t4;
            uint32_t ah[2][4], al[2][4], bh[4][2], bl[4][2];
#pragma unroll
            for (int mf = 0; mf < 2; mf++) {
                int rb = wm * 32 + mf * 16;
                ah[mf][0] = sAh[(rb + g) * 20 + base];
                ah[mf][1] = sAh[(rb + g + 8) * 20 + base];
                ah[mf][2] = sAh[(rb + g) * 20 + base + 4];
                ah[mf][3] = sAh[(rb + g + 8) * 20 + base + 4];
                al[mf][0] = sAl[(rb + g) * 20 + base];
                al[mf][1] = sAl[(rb + g + 8) * 20 + base];
                al[mf][2] = sAl[(rb + g) * 20 + base + 4];
                al[mf][3] = sAl[(rb + g + 8) * 20 + base + 4];
            }
#pragma unroll
            for (int nf = 0; nf < 4; nf++) {
                int nb = wn * 32 + nf * 8 + g;
                bh[nf][0] = sBh[nb * 20 + base];
                bh[nf][1] = sBh[nb * 20 + base + 4];
                bl[nf][0] = sBl[nb * 20 + base];
                bl[nf][1] = sBl[nb * 20 + base + 4];
            }
#pragma unroll
            for (int mf = 0; mf < 2; mf++)
#pragma unroll
                for (int nf = 0; nf < 4; nf++) {
                    mma_bf16(acc[mf][nf], ah[mf][0], ah[mf][1], ah[mf][2], ah[mf][3],
                             bh[nf][0], bh[nf][1]);
                    mma_bf16(acc[mf][nf], ah[mf][0], ah[mf][1], ah[mf][2], ah[mf][3],
                             bl[nf][0], bl[nf][1]);
                    mma_bf16(acc[mf][nf], al[mf][0], al[mf][1], al[mf][2], al[mf][3],
                             bh[nf][0], bh[nf][1]);
                }
        }
        __syncthreads();
    }

    // Epilogue
#pragma unroll
    for (int mf = 0; mf < 2; mf++)
#pragma unroll
        for (int nf = 0; nf < 4; nf++)
#pragma unroll
            for (int rr = 0; rr < 2; rr++)
#pragma unroll
                for (int cc = 0; cc < 2; cc++) {
                    int row = m0 + wm * 32 + mf * 16 + g + rr * 8;
                    int col = n0 + wn * 32 + nf * 8 + 2 * t4 + cc;
                    float v = acc[mf][nf][rr * 2 + cc] + bias[col];
                    if (mode == 0) {
                        __nv_bfloat16 h = __float2bfloat16(v);
                        g_t1hi[(size_t)row * N + col] = h;
                        g_t1lo[(size_t)row * N + col] =
                            __float2bfloat16(v - __bfloat162float(h));
                    } else if (mode == 1) {
                        outf[(size_t)row * N + col] = v;
                        __nv_bfloat16 h = __float2bfloat16(v);
                        g_hs_hi[(size_t)row * N + col] = h;
                        g_hs_lo[(size_t)row * N + col] =
                            __float2bfloat16(v - __bfloat162float(h));
                    } else {
                        int t = row >> 8;               // row = t*B + b
                        int b = row & 255;
                        int Trt = M >> 8;
                        outf[(size_t)b * Trt * N + (size_t)t * N + col] = v;
                    }
                }
}

// ---------------------------------------------------------------------------
// Fused GRU step, 4-stage cp.async pipeline.
// Per CTA: 128 batch rows x 16 hidden cols x 6 gates; grid (64, 2), 256 thr.
// Stage layout (u32, stride 20): Ah[128*20] Al[128*20] Bh[96*20] Bl[96*20]
// ---------------------------------------------------------------------------
#define R_SSZ  (448 * 20)                 // u32 per stage
#define R_SMEM (STAGES * R_SSZ * 4)       // 143360 bytes

__global__ __launch_bounds__(256) void gru_kernel(
    int t, const float* __restrict__ b_ih, const float* __restrict__ b_hh)
{
    extern __shared__ uint32_t smem[];

    int tid  = threadIdx.x;
    int lane = tid & 31, warp = tid >> 5;
    int g = lane >> 2, t4 = lane & 3;
    int m0 = blockIdx.y * 128;
    int j0 = blockIdx.x * 16;

    const uint32_t* Hh   = (const uint32_t*)g_hs_hi + (size_t)t * (B_ * H_ / 2);
    const uint32_t* Hl   = (const uint32_t*)g_hs_lo + (size_t)t * (B_ * H_ / 2);
    const uint32_t* W32h = (const uint32_t*)g_Whi;
    const uint32_t* W32l = (const uint32_t*)g_Wlo;
    uint32_t sbase = (uint32_t)__cvta_generic_to_shared(smem);

    auto load_tile = [&](int kt, int stage) {
        if (kt < 32) {
            int kc = kt * 16;
            uint32_t base = sbase + (uint32_t)stage * R_SSZ * 4;
#pragma unroll
            for (int i = 0; i < 4; i++) {          // A (h): 128 rows x 4 x 2
                int c = tid + i * 256;
                int half = c >> 9, rem = c & 511;
                int row = rem >> 2, ch = rem & 3;
                const uint32_t* src = (half ? Hl : Hh)
                                      + (size_t)(m0 + row) * 512 + kc + ch * 4;
                cp16(base + (uint32_t)(half * 128 * 20 + row * 20 + ch * 4) * 4, src);
            }
#pragma unroll
            for (int i = 0; i < 3; i++) {          // W: 96 rows x 4 x 2
                int c = tid + i * 256;
                int half = (c >= 384);
                int rem = half ? c - 384 : c;
                int row = rem >> 2, ch = rem & 3;
                int gate = row >> 4, rj = row & 15;
                const uint32_t* src = (half ? W32l : W32h)
                                      + ((size_t)gate * H_ + j0 + rj) * 512 + kc + ch * 4;
                cp16(base + (uint32_t)((256 + half * 96) * 20 + row * 20 + ch * 4) * 4, src);
            }
        }
        cp_commit();
    };

    float acc[6][2][4];
#pragma unroll
    for (int a = 0; a < 6; a++)
#pragma unroll
        for (int b = 0; b < 2; b++)
#pragma unroll
            for (int c = 0; c < 4; c++) acc[a][b][c] = 0.0f;

    for (int i = 0; i < STAGES - 1; i++) load_tile(i, i);

    for (int kt = 0; kt < 32; kt++) {
        cp_wait<STAGES - 2>();
        __syncthreads();
        load_tile(kt + STAGES - 1, (kt + STAGES - 1) & (STAGES - 1));

        const uint32_t* st  = smem + (kt & (STAGES - 1)) * R_SSZ;
        const uint32_t* sAh = st;
        const uint32_t* sAl = st + 128 * 20;
        const uint32_t* sBh = st + 256 * 20;
        const uint32_t* sBl = st + 352 * 20;

#pragma unroll
        for (int kk = 0; kk < 2; kk++) {
            int base = kk * 8 + t4;
            int rb = warp * 16;
            uint32_t ah[4], al[4];
            ah[0] = sAh[(rb + g) * 20 + base];
            ah[1] = sAh[(rb + g + 8) * 20 + base];
            ah[2] = sAh[(rb + g) * 20 + base + 4];
            ah[3] = sAh[(rb + g + 8) * 20 + base + 4];
            al[0] = sAl[(rb + g) * 20 + base];
            al[1] = sAl[(rb + g + 8) * 20 + base];
            al[2] = sAl[(rb + g) * 20 + base + 4];
            al[3] = sAl[(rb + g + 8) * 20 + base + 4];
#pragma unroll
            for (int gate = 0; gate < 6; gate++) {
#pragma unroll
                for (int nf = 0; nf < 2; nf++) {
                    int nb = gate * 16 + nf * 8 + g;
                    uint32_t b0h = sBh[nb * 20 + base];
                    uint32_t b1h = sBh[nb * 20 + base + 4];
                    uint32_t b0l = sBl[nb * 20 + base];
                    uint32_t b1l = sBl[nb * 20 + base + 4];
                    mma_bf16(acc[gate][nf], ah[0], ah[1], ah[2], ah[3], b0h, b1h);
                    mma_bf16(acc[gate][nf], ah[0], ah[1], ah[2], ah[3], b0l, b1l);
                    mma_bf16(acc[gate][nf], al[0], al[1], al[2], al[3], b0h, b1h);
                }
            }
        }
        __syncthreads();
    }

    // Epilogue: gate math + state update, split-write h_{t+1}.
    const __nv_bfloat16* src_hi = g_hs_hi + (size_t)t * B_ * H_;
    const __nv_bfloat16* src_lo = g_hs_lo + (size_t)t * B_ * H_;
    __nv_bfloat16* dst_hi = g_hs_hi + (size_t)(t + 1) * B_ * H_;
    __nv_bfloat16* dst_lo = g_hs_lo + (size_t)(t + 1) * B_ * H_;

#pragma unroll
    for (int nf = 0; nf < 2; nf++)
#pragma unroll
        for (int cc = 0; cc < 2; cc++) {
            int j = j0 + nf * 8 + 2 * t4 + cc;
            float bir = b_ih[j], biz = b_ih[H_ + j], bin = b_ih[2 * H_ + j];
            float bhr = b_hh[j], bhz = b_hh[H_ + j], bhn = b_hh[2 * H_ + j];
#pragma unroll
            for (int rr = 0; rr < 2; rr++) {
                int m  = m0 + warp * 16 + g + rr * 8;
                int ci = rr * 2 + cc;
                float ir  = acc[0][nf][ci] + bir;
                float iz  = acc[1][nf][ci] + biz;
                float inn = acc[2][nf][ci] + bin;
                float hr  = acc[3][nf][ci] + bhr;
                float hz  = acc[4][nf][ci] + bhz;
                float hn  = acc[5][nf][ci] + bhn;
                float r  = sigm(ir + hr);
                float z  = sigm(iz + hz);
                float nn = tanh_fast(inn + r * hn);
                size_t idx = (size_t)m * H_ + j;
                float hold = __bfloat162float(src_hi[idx]) + __bfloat162float(src_lo[idx]);
                float hnew = (1.0f - z) * nn + z * hold;
                __nv_bfloat16 hh = __float2bfloat16(hnew);
                dst_hi[idx] = hh;
                dst_lo[idx] = __float2bfloat16(hnew - __bfloat162float(hh));
            }
        }
}

// ---------------------------------------------------------------------------
// Host launcher: graph-capturable.
// ---------------------------------------------------------------------------
extern "C" void kernel_launch(void* const* d_in, const int* in_sizes, int n_in,
                              void* d_out, int out_size) {
    const float* x     = (const float*)d_in[0];
    const float* w1    = (const float*)d_in[1];
    const float* b1    = (const float*)d_in[2];
    const float* w2    = (const float*)d_in[3];
    const float* b2    = (const float*)d_in[4];
    const float* w_ih  = (const float*)d_in[5];
    const float* b_ih  = (const float*)d_in[6];
    const float* w_hh  = (const float*)d_in[7];
    const float* b_hh  = (const float*)d_in[8];
    const float* out_w = (const float*)d_in[9];
    const float* out_b = (const float*)d_in[10];
    float* out = (float*)d_out;

    int T = (out_size - B_ * H_) / (B_ * DOUT_);   // = 256
    if (T > T_) T = T_;

    static bool attr_done = false;
    if (!attr_done) {
        cudaFuncSetAttribute(gemm3_kernel,
                             cudaFuncAttributeMaxDynamicSharedMemorySize, G_SMEM);
        cudaFuncSetAttribute(gru_kernel,
                             cudaFuncAttributeMaxDynamicSharedMemorySize, R_SMEM);
        attr_done = true;
    }

    split_kernel<<<(B_ * DIN_ + 255) / 256, 256>>>(0, x, B_ * DIN_);
    split_kernel<<<(H_ * DIN_ + 255) / 256, 256>>>(1, w1, H_ * DIN_);
    split_kernel<<<(H_ * H_ + 255) / 256, 256>>>(2, w2, H_ * H_);
    split_kernel<<<(3 * H_ * H_ + 255) / 256, 256>>>(3, w_ih, 3 * H_ * H_);
    split_kernel<<<(3 * H_ * H_ + 255) / 256, 256>>>(4, w_hh, 3 * H_ * H_);
    split_kernel<<<(DOUT_ * H_ + 255) / 256, 256>>>(5, out_w, DOUT_ * H_);

    // FCN layer 1: t1 = x @ w1^T + b1
    gemm3_kernel<<<dim3(H_ / 64, B_ / 128), 256, G_SMEM>>>(0, b1, nullptr,
                                                           B_, H_, DIN_, 0);
    // FCN layer 2: latent -> d_out latent slice + hs slab 0
    gemm3_kernel<<<dim3(H_ / 64, B_ / 128), 256, G_SMEM>>>(
        1, b2, out + (size_t)B_ * T * DOUT_, B_, H_, H_, 1);

    // GRU recurrence
    for (int t = 0; t < T; t++)
        gru_kernel<<<dim3(H_ / 16, B_ / 128), 256, R_SMEM>>>(t, b_ih, b_hh);

    // Output projection (permuted write)
    gemm3_kernel<<<dim3(DOUT_ / 64, (T * B_) / 128), 256, G_SMEM>>>(
        2, out_b, out, T * B_, DOUT_, H_, 2);
}

// round 3
// speedup vs baseline: 1.3519x; 1.3519x over previous
#include <cuda_runtime.h>
#include <cuda_bf16.h>
#include <cstdint>
#include <cstddef>

// Problem constants (shapes fixed by the dataset).
#define B_    256
#define DIN_  512
#define H_    1024
#define DOUT_ 512
#define T_    256

// ---------------------------------------------------------------------------
// Device scratch. hs: T+1 slabs of [B, H] split bf16 (hi+lo).
// ---------------------------------------------------------------------------
__device__ __nv_bfloat16 g_hs_hi[(size_t)(T_ + 1) * B_ * H_];
__device__ __nv_bfloat16 g_hs_lo[(size_t)(T_ + 1) * B_ * H_];
__device__ __nv_bfloat16 g_Whi[6 * H_ * H_];   // rows: [w_ih(3H); w_hh(3H)] x H
__device__ __nv_bfloat16 g_Wlo[6 * H_ * H_];
__device__ __nv_bfloat16 g_xhi[B_ * DIN_],  g_xlo[B_ * DIN_];
__device__ __nv_bfloat16 g_w1hi[H_ * DIN_], g_w1lo[H_ * DIN_];
__device__ __nv_bfloat16 g_w2hi[H_ * H_],   g_w2lo[H_ * H_];
__device__ __nv_bfloat16 g_t1hi[B_ * H_],   g_t1lo[B_ * H_];
__device__ __nv_bfloat16 g_owhi[DOUT_ * H_], g_owlo[DOUT_ * H_];

// ---------------------------------------------------------------------------
// Fused split: all 6 fp32 tensors -> bf16 hi/lo in ONE launch (so that the
// GRU kernel lands on ncu's fixed launch-skip slot, and less launch overhead).
// Segment boundaries (element counts):
//   x 131072 | w1 524288 | w2 1048576 | w_ih 3145728 | w_hh 3145728 | ow 524288
// ---------------------------------------------------------------------------
#define SPLIT_TOTAL 8519680
__global__ void split_all_kernel(const float* __restrict__ x,
                                 const float* __restrict__ w1,
                                 const float* __restrict__ w2,
                                 const float* __restrict__ wih,
                                 const float* __restrict__ whh,
                                 const float* __restrict__ ow) {
    int i = blockIdx.x * blockDim.x + threadIdx.x;
    if (i >= SPLIT_TOTAL) return;
    const float* src;
    __nv_bfloat16 *hi, *lo;
    int off;
    if (i < 131072)        { src = x;   hi = g_xhi;  lo = g_xlo;  off = i; }
    else if (i < 655360)   { src = w1;  hi = g_w1hi; lo = g_w1lo; off = i - 131072; }
    else if (i < 1703936)  { src = w2;  hi = g_w2hi; lo = g_w2lo; off = i - 655360; }
    else if (i < 4849664)  { src = wih; hi = g_Whi;  lo = g_Wlo;  off = i - 1703936; }
    else if (i < 7995392)  { src = whh; hi = g_Whi + 3 * H_ * H_;
                             lo = g_Wlo + 3 * H_ * H_; off = i - 4849664; }
    else                   { src = ow;  hi = g_owhi; lo = g_owlo; off = i - 7995392; }
    float v = src[off];
    __nv_bfloat16 h = __float2bfloat16(v);
    hi[off] = h;
    lo[off] = __float2bfloat16(v - __bfloat162float(h));
}

// ---------------------------------------------------------------------------
// PTX helpers
// ---------------------------------------------------------------------------
__device__ __forceinline__ void mma_bf16(float* c,
                                         uint32_t a0, uint32_t a1, uint32_t a2, uint32_t a3,
                                         uint32_t b0, uint32_t b1) {
    asm volatile(
        "mma.sync.aligned.m16n8k16.row.col.f32.bf16.bf16.f32 "
        "{%0,%1,%2,%3}, {%4,%5,%6,%7}, {%8,%9}, {%0,%1,%2,%3};\n"
        : "+f"(c[0]), "+f"(c[1]), "+f"(c[2]), "+f"(c[3])
        : "r"(a0), "r"(a1), "r"(a2), "r"(a3), "r"(b0), "r"(b1));
}
__device__ __forceinline__ void ldsm4(uint32_t& r0, uint32_t& r1,
                                      uint32_t& r2, uint32_t& r3, uint32_t addr) {
    asm volatile("ldmatrix.sync.aligned.m8n8.x4.shared.b16 {%0,%1,%2,%3}, [%4];\n"
                 : "=r"(r0), "=r"(r1), "=r"(r2), "=r"(r3) : "r"(addr));
}
__device__ __forceinline__ float sigm(float x) { return 1.0f / (1.0f + __expf(-x)); }
__device__ __forceinline__ float tanh_fast(float x) {
    float a = fabsf(x);
    float e = __expf(-2.0f * a);
    return copysignf((1.0f - e) / (1.0f + e), x);
}

// ---------------------------------------------------------------------------
// Split-bf16 GEMM (round-0 proven version, static smem).
// C[M,N] = A[M,K] @ B[N,K]^T + bias[N]; BM=128, BN=64, BK=32; 256 threads.
// ---------------------------------------------------------------------------
__global__ __launch_bounds__(256) void gemm3_kernel(
    int which, const float* __restrict__ bias, float* __restrict__ outf,
    int M, int N, int K, int mode)
{
    const __nv_bfloat16 *Ahi, *Alo, *Bhi, *Blo;
    if (which == 0)      { Ahi = g_xhi;  Alo = g_xlo;  Bhi = g_w1hi; Blo = g_w1lo; }
    else if (which == 1) { Ahi = g_t1hi; Alo = g_t1lo; Bhi = g_w2hi; Blo = g_w2lo; }
    else                 { Ahi = g_hs_hi + (size_t)B_ * H_; Alo = g_hs_lo + (size_t)B_ * H_;
                           Bhi = g_owhi; Blo = g_owlo; }
    const uint32_t* A32h = (const uint32_t*)Ahi;
    const uint32_t* A32l = (const uint32_t*)Alo;
    const uint32_t* B32h = (const uint32_t*)Bhi;
    const uint32_t* B32l = (const uint32_t*)Blo;

    __shared__ uint32_t sAh[128 * 20], sAl[128 * 20];
    __shared__ uint32_t sBh[64 * 20],  sBl[64 * 20];

    int tid  = threadIdx.x;
    int lane = tid & 31, warp = tid >> 5;
    int g = lane >> 2, t4 = lane & 3;
    int wm = warp >> 1, wn = warp & 1;
    int m0 = blockIdx.y * 128;
    int n0 = blockIdx.x * 64;
    int K2 = K >> 1;

    float acc[2][4][4];
#pragma unroll
    for (int a = 0; a < 2; a++)
#pragma unroll
        for (int b = 0; b < 4; b++)
#pragma unroll
            for (int c = 0; c < 4; c++) acc[a][b][c] = 0.0f;

    for (int k0 = 0; k0 < K; k0 += 32) {
        __syncthreads();
        int kc = k0 >> 1;
#pragma unroll
        for (int i = 0; i < 8; i++) {
            int e = tid + i * 256;
            int r = e >> 4, c = e & 15;
            size_t gi = (size_t)(m0 + r) * K2 + kc + c;
            sAh[r * 20 + c] = A32h[gi];
            sAl[r * 20 + c] = A32l[gi];
        }
#pragma unroll
        for (int i = 0; i < 4; i++) {
            int e = tid + i * 256;
            int r = e >> 4, c = e & 15;
            size_t gi = (size_t)(n0 + r) * K2 + kc + c;
            sBh[r * 20 + c] = B32h[gi];
            sBl[r * 20 + c] = B32l[gi];
        }
        __syncthreads();

#pragma unroll
        for (int kk = 0; kk < 2; kk++) {
            int base = kk * 8 + t4;
            uint32_t ah[2][4], al[2][4], bh[4][2], bl[4][2];
#pragma unroll
            for (int mf = 0; mf < 2; mf++) {
                int rb = wm * 32 + mf * 16;
                ah[mf][0] = sAh[(rb + g) * 20 + base];
                ah[mf][1] = sAh[(rb + g + 8) * 20 + base];
                ah[mf][2] = sAh[(rb + g) * 20 + base + 4];
                ah[mf][3] = sAh[(rb + g + 8) * 20 + base + 4];
                al[mf][0] = sAl[(rb + g) * 20 + base];
                al[mf][1] = sAl[(rb + g + 8) * 20 + base];
                al[mf][2] = sAl[(rb + g) * 20 + base + 4];
                al[mf][3] = sAl[(rb + g + 8) * 20 + base + 4];
            }
#pragma unroll
            for (int nf = 0; nf < 4; nf++) {
                int nb = wn * 32 + nf * 8 + g;
                bh[nf][0] = sBh[nb * 20 + base];
                bh[nf][1] = sBh[nb * 20 + base + 4];
                bl[nf][0] = sBl[nb * 20 + base];
                bl[nf][1] = sBl[nb * 20 + base + 4];
            }
#pragma unroll
            for (int mf = 0; mf < 2; mf++)
#pragma unroll
                for (int nf = 0; nf < 4; nf++) {
                    mma_bf16(acc[mf][nf], ah[mf][0], ah[mf][1], ah[mf][2], ah[mf][3],
                             bh[nf][0], bh[nf][1]);
                    mma_bf16(acc[mf][nf], ah[mf][0], ah[mf][1], ah[mf][2], ah[mf][3],
                             bl[nf][0], bl[nf][1]);
                    mma_bf16(acc[mf][nf], al[mf][0], al[mf][1], al[mf][2], al[mf][3],
                             bh[nf][0], bh[nf][1]);
                }
        }
    }

#pragma unroll
    for (int mf = 0; mf < 2; mf++)
#pragma unroll
        for (int nf = 0; nf < 4; nf++)
#pragma unroll
            for (int rr = 0; rr < 2; rr++)
#pragma unroll
                for (int cc = 0; cc < 2; cc++) {
                    int row = m0 + wm * 32 + mf * 16 + g + rr * 8;
                    int col = n0 + wn * 32 + nf * 8 + 2 * t4 + cc;
                    float v = acc[mf][nf][rr * 2 + cc] + bias[col];
                    if (mode == 0) {
                        __nv_bfloat16 h = __float2bfloat16(v);
                        g_t1hi[(size_t)row * N + col] = h;
                        g_t1lo[(size_t)row * N + col] =
                            __float2bfloat16(v - __bfloat162float(h));
                    } else if (mode == 1) {
                        outf[(size_t)row * N + col] = v;
                        __nv_bfloat16 h = __float2bfloat16(v);
                        g_hs_hi[(size_t)row * N + col] = h;
                        g_hs_lo[(size_t)row * N + col] =
                            __float2bfloat16(v - __bfloat162float(h));
                    } else {
                        int t = row >> 8;               // row = t*B + b
                        int b = row & 255;
                        int Trt = M >> 8;
                        outf[(size_t)b * Trt * N + (size_t)t * N + col] = v;
                    }
                }
}

// ---------------------------------------------------------------------------
// Fused GRU step: register-double-buffered global loads + LDSM fragment loads.
// Per CTA: 128 batch rows x 16 hidden cols x 6 gates; grid (64, 2), 256 thr.
// Smem: 2 buffers, each (u32, stride 20): Ah[128*20] Al[128*20] Bh[96*20] Bl[96*20]
// Each thread loads exactly 7 x 16B chunks per tile (A:4, B:3).
// ---------------------------------------------------------------------------
#define R_BUF   (448 * 20)                // u32 per buffer
#define R_SMEM  (2 * R_BUF * 4)           // 71680 bytes dynamic

__global__ __launch_bounds__(256) void gru_kernel(
    int t, const float* __restrict__ b_ih, const float* __restrict__ b_hh)
{
    extern __shared__ uint32_t smem[];

    int tid  = threadIdx.x;
    int lane = tid & 31, warp = tid >> 5;
    int g = lane >> 2, t4 = lane & 3;
    int m0 = blockIdx.y * 128;
    int j0 = blockIdx.x * 16;
    int rb = warp * 16;
    uint32_t sb = (uint32_t)__cvta_generic_to_shared(smem);

    // ---- per-thread global-load plan: 7 chunks of 16B ----
    const uint4* srcp[7];
    uint32_t     soff[7];                  // u32 offset within a buffer
#pragma unroll
    for (int i = 0; i < 7; i++) {
        int c = tid + i * 256;             // 0..1791
        if (c < 1024) {                    // A (h): hi then lo, 128 rows x 4 chunks
            int half = c >> 9, rem = c & 511;
            int row = rem >> 2, ch = rem & 3;
            const __nv_bfloat16* base =
                (half ? g_hs_lo : g_hs_hi) + (size_t)t * B_ * H_;
            srcp[i] = (const uint4*)base + (size_t)(m0 + row) * 128 + ch;
            soff[i] = half * 2560 + row * 20 + ch * 4;
        } else {                           // W: hi then lo, 96 rows x 4 chunks
            int c2 = c - 1024;
            int half = (c2 >= 384);
            int rem = half ? c2 - 384 : c2;
            int row = rem >> 2, ch = rem & 3;
            int gate = row >> 4, rj = row & 15;
            const __nv_bfloat16* base = half ? g_Wlo : g_Whi;
            srcp[i] = (const uint4*)base + (size_t)(gate * H_ + j0 + rj) * 128 + ch;
            soff[i] = 5120 + half * 1920 + row * 20 + ch * 4;
        }
    }

    // LDSM address bases (byte offsets within a buffer)
    uint32_t a_base = (uint32_t)((rb + (lane & 15)) * 80 + (lane >> 4) * 16);
    int q = lane >> 3;
    uint32_t b_base = (uint32_t)(20480 + (lane & 7) * 80 + (q >> 1) * 32 + (q & 1) * 16);

    float acc[6][2][4];
#pragma unroll
    for (int a = 0; a < 6; a++)
#pragma unroll
        for (int b = 0; b < 2; b++)
#pragma unroll
            for (int c = 0; c < 4; c++) acc[a][b][c] = 0.0f;

    uint4 pf[7];
    // Prologue: tile 0 -> regs -> buf 0
#pragma unroll
    for (int i = 0; i < 7; i++) pf[i] = srcp[i][0];
#pragma unroll
    for (int i = 0; i < 7; i++)
        *(uint4*)(smem + soff[i]) = pf[i];
    __syncthreads();

    for (int kt = 0; kt < 32; kt++) {
        // Prefetch next tile into registers (latency hidden under MMAs)
        if (kt + 1 < 32) {
#pragma unroll
            for (int i = 0; i < 7; i++) pf[i] = srcp[i][(kt + 1) * 4];
        }

        uint32_t bufB = sb + (uint32_t)(kt & 1) * (R_BUF * 4);

        // A fragments via LDSM.x4 (hi and lo, both k16 chunks)
        uint32_t ah[2][4], al[2][4];
#pragma unroll
        for (int kk = 0; kk < 2; kk++) {
            uint32_t aaddr = bufB + a_base + kk * 32;
            ldsm4(ah[kk][0], ah[kk][1], ah[kk][2], ah[kk][3], aaddr);
            ldsm4(al[kk][0], al[kk][1], al[kk][2], al[kk][3], aaddr + 10240);
        }

#pragma unroll
        for (int gate = 0; gate < 6; gate++) {
#pragma unroll
            for (int nf = 0; nf < 2; nf++) {
                uint32_t baddr = bufB + b_base + (uint32_t)((gate * 16 + nf * 8) * 80);
                uint32_t bh0, bh1, bh2, bh3, bl0, bl1, bl2, bl3;
                ldsm4(bh0, bh1, bh2, bh3, baddr);          // {b0,b1}kk0, {b0,b1}kk1 hi
                ldsm4(bl0, bl1, bl2, bl3, baddr + 7680);   // same, lo
                mma_bf16(acc[gate][nf], ah[0][0], ah[0][1], ah[0][2], ah[0][3], bh0, bh1);
                mma_bf16(acc[gate][nf], ah[0][0], ah[0][1], ah[0][2], ah[0][3], bl0, bl1);
                mma_bf16(acc[gate][nf], al[0][0], al[0][1], al[0][2], al[0][3], bh0, bh1);
                mma_bf16(acc[gate][nf], ah[1][0], ah[1][1], ah[1][2], ah[1][3], bh2, bh3);
                mma_bf16(acc[gate][nf], ah[1][0], ah[1][1], ah[1][2], ah[1][3], bl2, bl3);
                mma_bf16(acc[gate][nf], al[1][0], al[1][1], al[1][2], al[1][3], bh2, bh3);
            }
        }

        // Store prefetched tile into the other buffer
        if (kt + 1 < 32) {
            uint32_t* dst = smem + ((kt + 1) & 1) * R_BUF;
#pragma unroll
            for (int i = 0; i < 7; i++)
                *(uint4*)(dst + soff[i]) = pf[i];
        }
        __syncthreads();
    }

    // Epilogue: gate math + state update, split-write h_{t+1}.
    const __nv_bfloat16* src_hi = g_hs_hi + (size_t)t * B_ * H_;
    const __nv_bfloat16* src_lo = g_hs_lo + (size_t)t * B_ * H_;
    __nv_bfloat16* dst_hi = g_hs_hi + (size_t)(t + 1) * B_ * H_;
    __nv_bfloat16* dst_lo = g_hs_lo + (size_t)(t + 1) * B_ * H_;

#pragma unroll
    for (int nf = 0; nf < 2; nf++)
#pragma unroll
        for (int cc = 0; cc < 2; cc++) {
            int j = j0 + nf * 8 + 2 * t4 + cc;
            float bir = b_ih[j], biz = b_ih[H_ + j], bin = b_ih[2 * H_ + j];
            float bhr = b_hh[j], bhz = b_hh[H_ + j], bhn = b_hh[2 * H_ + j];
#pragma unroll
            for (int rr = 0; rr < 2; rr++) {
                int m  = m0 + warp * 16 + g + rr * 8;
                int ci = rr * 2 + cc;
                float ir  = acc[0][nf][ci] + bir;
                float iz  = acc[1][nf][ci] + biz;
                float inn = acc[2][nf][ci] + bin;
                float hr  = acc[3][nf][ci] + bhr;
                float hz  = acc[4][nf][ci] + bhz;
                float hn  = acc[5][nf][ci] + bhn;
                float r  = sigm(ir + hr);
                float z  = sigm(iz + hz);
                float nn = tanh_fast(inn + r * hn);
                size_t idx = (size_t)m * H_ + j;
                float hold = __bfloat162float(src_hi[idx]) + __bfloat162float(src_lo[idx]);
                float hnew = (1.0f - z) * nn + z * hold;
                __nv_bfloat16 hh = __float2bfloat16(hnew);
                dst_hi[idx] = hh;
                dst_lo[idx] = __float2bfloat16(hnew - __bfloat162float(hh));
            }
        }
}

// ---------------------------------------------------------------------------
// Host launcher: graph-capturable.
// Launch order: split_all(0), gemm(1), gemm(2), gru t=0.. (3,4,5,...) so the
// fixed ncu skip (-s 5) profiles gru_kernel next round.
// ---------------------------------------------------------------------------
extern "C" void kernel_launch(void* const* d_in, const int* in_sizes, int n_in,
                              void* d_out, int out_size) {
    const float* x     = (const float*)d_in[0];
    const float* w1    = (const float*)d_in[1];
    const float* b1    = (const float*)d_in[2];
    const float* w2    = (const float*)d_in[3];
    const float* b2    = (const float*)d_in[4];
    const float* w_ih  = (const float*)d_in[5];
    const float* b_ih  = (const float*)d_in[6];
    const float* w_hh  = (const float*)d_in[7];
    const float* b_hh  = (const float*)d_in[8];
    const float* out_w = (const float*)d_in[9];
    const float* out_b = (const float*)d_in[10];
    float* out = (float*)d_out;

    int T = (out_size - B_ * H_) / (B_ * DOUT_);   // = 256
    if (T > T_) T = T_;

    static bool attr_done = false;
    if (!attr_done) {
        cudaFuncSetAttribute(gru_kernel,
                             cudaFuncAttributeMaxDynamicSharedMemorySize, R_SMEM);
        attr_done = true;
    }

    split_all_kernel<<<(SPLIT_TOTAL + 255) / 256, 256>>>(x, w1, w2, w_ih, w_hh, out_w);

    // FCN layer 1: t1 = x @ w1^T + b1
    gemm3_kernel<<<dim3(H_ / 64, B_ / 128), 256>>>(0, b1, nullptr, B_, H_, DIN_, 0);
    // FCN layer 2: latent -> d_out latent slice + hs slab 0
    gemm3_kernel<<<dim3(H_ / 64, B_ / 128), 256>>>(
        1, b2, out + (size_t)B_ * T * DOUT_, B_, H_, H_, 1);

    // GRU recurrence
    for (int t = 0; t < T; t++)
        gru_kernel<<<dim3(H_ / 16, B_ / 128), 256, R_SMEM>>>(t, b_ih, b_hh);

    // Output projection (permuted write)
    gemm3_kernel<<<dim3(DOUT_ / 64, (T * B_) / 128), 256>>>(
        2, out_b, out, T * B_, DOUT_, H_, 2);
}

// round 4
// speedup vs baseline: 1.3876x; 1.0264x over previous
#include <cuda_runtime.h>
#include <cuda_bf16.h>
#include <cstdint>
#include <cstddef>

// Problem constants (shapes fixed by the dataset).
#define B_    256
#define DIN_  512
#define H_    1024
#define DOUT_ 512
#define T_    256

// ---------------------------------------------------------------------------
// Device scratch. hs: T+1 slabs of [B, H] split bf16 (hi+lo).
// ---------------------------------------------------------------------------
__device__ __nv_bfloat16 g_hs_hi[(size_t)(T_ + 1) * B_ * H_];
__device__ __nv_bfloat16 g_hs_lo[(size_t)(T_ + 1) * B_ * H_];
__device__ __nv_bfloat16 g_Whi[6 * H_ * H_];   // rows: [w_ih(3H); w_hh(3H)] x H
__device__ __nv_bfloat16 g_Wlo[6 * H_ * H_];
__device__ __nv_bfloat16 g_xhi[B_ * DIN_],  g_xlo[B_ * DIN_];
__device__ __nv_bfloat16 g_w1hi[H_ * DIN_], g_w1lo[H_ * DIN_];
__device__ __nv_bfloat16 g_w2hi[H_ * H_],   g_w2lo[H_ * H_];
__device__ __nv_bfloat16 g_t1hi[B_ * H_],   g_t1lo[B_ * H_];
__device__ __nv_bfloat16 g_owhi[DOUT_ * H_], g_owlo[DOUT_ * H_];

// ---------------------------------------------------------------------------
// Fused split: all 6 fp32 tensors -> bf16 hi/lo in one launch.
// ---------------------------------------------------------------------------
#define SPLIT_TOTAL 8519680
__global__ void split_all_kernel(const float* __restrict__ x,
                                 const float* __restrict__ w1,
                                 const float* __restrict__ w2,
                                 const float* __restrict__ wih,
                                 const float* __restrict__ whh,
                                 const float* __restrict__ ow) {
    int i = blockIdx.x * blockDim.x + threadIdx.x;
    if (i >= SPLIT_TOTAL) return;
    const float* src;
    __nv_bfloat16 *hi, *lo;
    int off;
    if (i < 131072)        { src = x;   hi = g_xhi;  lo = g_xlo;  off = i; }
    else if (i < 655360)   { src = w1;  hi = g_w1hi; lo = g_w1lo; off = i - 131072; }
    else if (i < 1703936)  { src = w2;  hi = g_w2hi; lo = g_w2lo; off = i - 655360; }
    else if (i < 4849664)  { src = wih; hi = g_Whi;  lo = g_Wlo;  off = i - 1703936; }
    else if (i < 7995392)  { src = whh; hi = g_Whi + 3 * H_ * H_;
                             lo = g_Wlo + 3 * H_ * H_; off = i - 4849664; }
    else                   { src = ow;  hi = g_owhi; lo = g_owlo; off = i - 7995392; }
    float v = src[off];
    __nv_bfloat16 h = __float2bfloat16(v);
    hi[off] = h;
    lo[off] = __float2bfloat16(v - __bfloat162float(h));
}

// ---------------------------------------------------------------------------
// PTX helpers
// ---------------------------------------------------------------------------
__device__ __forceinline__ void mma_bf16(float* c,
                                         uint32_t a0, uint32_t a1, uint32_t a2, uint32_t a3,
                                         uint32_t b0, uint32_t b1) {
    asm volatile(
        "mma.sync.aligned.m16n8k16.row.col.f32.bf16.bf16.f32 "
        "{%0,%1,%2,%3}, {%4,%5,%6,%7}, {%8,%9}, {%0,%1,%2,%3};\n"
        : "+f"(c[0]), "+f"(c[1]), "+f"(c[2]), "+f"(c[3])
        : "r"(a0), "r"(a1), "r"(a2), "r"(a3), "r"(b0), "r"(b1));
}
__device__ __forceinline__ void ldsm4(uint32_t& r0, uint32_t& r1,
                                      uint32_t& r2, uint32_t& r3, uint32_t addr) {
    asm volatile("ldmatrix.sync.aligned.m8n8.x4.shared.b16 {%0,%1,%2,%3}, [%4];\n"
                 : "=r"(r0), "=r"(r1), "=r"(r2), "=r"(r3) : "r"(addr));
}
__device__ __forceinline__ float sigm(float x) { return 1.0f / (1.0f + __expf(-x)); }
__device__ __forceinline__ float tanh_fast(float x) {
    float a = fabsf(x);
    float e = __expf(-2.0f * a);
    return copysignf((1.0f - e) / (1.0f + e), x);
}

// ---------------------------------------------------------------------------
// Split-bf16 GEMM; product-major MMA interleave (8 independent acc chains,
// same-acc reuse distance = 8 issues). BM=128, BN=64, BK=32; 256 threads.
// ---------------------------------------------------------------------------
__global__ __launch_bounds__(256, 2) void gemm3_kernel(
    int which, const float* __restrict__ bias, float* __restrict__ outf,
    int M, int N, int K, int mode)
{
    const __nv_bfloat16 *Ahi, *Alo, *Bhi, *Blo;
    if (which == 0)      { Ahi = g_xhi;  Alo = g_xlo;  Bhi = g_w1hi; Blo = g_w1lo; }
    else if (which == 1) { Ahi = g_t1hi; Alo = g_t1lo; Bhi = g_w2hi; Blo = g_w2lo; }
    else                 { Ahi = g_hs_hi + (size_t)B_ * H_; Alo = g_hs_lo + (size_t)B_ * H_;
                           Bhi = g_owhi; Blo = g_owlo; }
    const uint32_t* A32h = (const uint32_t*)Ahi;
    const uint32_t* A32l = (const uint32_t*)Alo;
    const uint32_t* B32h = (const uint32_t*)Bhi;
    const uint32_t* B32l = (const uint32_t*)Blo;

    __shared__ uint32_t sAh[128 * 20], sAl[128 * 20];
    __shared__ uint32_t sBh[64 * 20],  sBl[64 * 20];

    int tid  = threadIdx.x;
    int lane = tid & 31, warp = tid >> 5;
    int g = lane >> 2, t4 = lane & 3;
    int wm = warp >> 1, wn = warp & 1;
    int m0 = blockIdx.y * 128;
    int n0 = blockIdx.x * 64;
    int K2 = K >> 1;

    float acc[2][4][4];
#pragma unroll
    for (int a = 0; a < 2; a++)
#pragma unroll
        for (int b = 0; b < 4; b++)
#pragma unroll
            for (int c = 0; c < 4; c++) acc[a][b][c] = 0.0f;

    for (int k0 = 0; k0 < K; k0 += 32) {
        __syncthreads();
        int kc = k0 >> 1;
#pragma unroll
        for (int i = 0; i < 8; i++) {
            int e = tid + i * 256;
            int r = e >> 4, c = e & 15;
            size_t gi = (size_t)(m0 + r) * K2 + kc + c;
            sAh[r * 20 + c] = A32h[gi];
            sAl[r * 20 + c] = A32l[gi];
        }
#pragma unroll
        for (int i = 0; i < 4; i++) {
            int e = tid + i * 256;
            int r = e >> 4, c = e & 15;
            size_t gi = (size_t)(n0 + r) * K2 + kc + c;
            sBh[r * 20 + c] = B32h[gi];
            sBl[r * 20 + c] = B32l[gi];
        }
        __syncthreads();

#pragma unroll
        for (int kk = 0; kk < 2; kk++) {
            int base = kk * 8 + t4;
            uint32_t ah[2][4], al[2][4], bh[4][2], bl[4][2];
#pragma unroll
            for (int mf = 0; mf < 2; mf++) {
                int rb = wm * 32 + mf * 16;
                ah[mf][0] = sAh[(rb + g) * 20 + base];
                ah[mf][1] = sAh[(rb + g + 8) * 20 + base];
                ah[mf][2] = sAh[(rb + g) * 20 + base + 4];
                ah[mf][3] = sAh[(rb + g + 8) * 20 + base + 4];
                al[mf][0] = sAl[(rb + g) * 20 + base];
                al[mf][1] = sAl[(rb + g + 8) * 20 + base];
                al[mf][2] = sAl[(rb + g) * 20 + base + 4];
                al[mf][3] = sAl[(rb + g + 8) * 20 + base + 4];
            }
#pragma unroll
            for (int nf = 0; nf < 4; nf++) {
                int nb = wn * 32 + nf * 8 + g;
                bh[nf][0] = sBh[nb * 20 + base];
                bh[nf][1] = sBh[nb * 20 + base + 4];
                bl[nf][0] = sBl[nb * 20 + base];
                bl[nf][1] = sBl[nb * 20 + base + 4];
            }
            // product-major: 8 independent chains between same-acc reuses
#pragma unroll
            for (int mf = 0; mf < 2; mf++)
#pragma unroll
                for (int nf = 0; nf < 4; nf++)
                    mma_bf16(acc[mf][nf], ah[mf][0], ah[mf][1], ah[mf][2], ah[mf][3],
                             bh[nf][0], bh[nf][1]);
#pragma unroll
            for (int mf = 0; mf < 2; mf++)
#pragma unroll
                for (int nf = 0; nf < 4; nf++)
                    mma_bf16(acc[mf][nf], ah[mf][0], ah[mf][1], ah[mf][2], ah[mf][3],
                             bl[nf][0], bl[nf][1]);
#pragma unroll
            for (int mf = 0; mf < 2; mf++)
#pragma unroll
                for (int nf = 0; nf < 4; nf++)
                    mma_bf16(acc[mf][nf], al[mf][0], al[mf][1], al[mf][2], al[mf][3],
                             bh[nf][0], bh[nf][1]);
        }
    }

#pragma unroll
    for (int mf = 0; mf < 2; mf++)
#pragma unroll
        for (int nf = 0; nf < 4; nf++)
#pragma unroll
            for (int rr = 0; rr < 2; rr++)
#pragma unroll
                for (int cc = 0; cc < 2; cc++) {
                    int row = m0 + wm * 32 + mf * 16 + g + rr * 8;
                    int col = n0 + wn * 32 + nf * 8 + 2 * t4 + cc;
                    float v = acc[mf][nf][rr * 2 + cc] + bias[col];
                    if (mode == 0) {
                        __nv_bfloat16 h = __float2bfloat16(v);
                        g_t1hi[(size_t)row * N + col] = h;
                        g_t1lo[(size_t)row * N + col] =
                            __float2bfloat16(v - __bfloat162float(h));
                    } else if (mode == 1) {
                        outf[(size_t)row * N + col] = v;
                        __nv_bfloat16 h = __float2bfloat16(v);
                        g_hs_hi[(size_t)row * N + col] = h;
                        g_hs_lo[(size_t)row * N + col] =
                            __float2bfloat16(v - __bfloat162float(h));
                    } else {
                        int t = row >> 8;               // row = t*B + b
                        int b = row & 255;
                        int Trt = M >> 8;
                        outf[(size_t)b * Trt * N + (size_t)t * N + col] = v;
                    }
                }
}

// ---------------------------------------------------------------------------
// Fused GRU step.
// This round: explicit MMA chain interleaving. Gates processed in 2 halves of
// 6 independent (gate,nf) accumulator chains; 6 interleave passes ensure the
// same-acc reuse distance is 6 MMA issues (> HMMA latency). Register file is
// free (grid=128 -> 1 CTA/SM), so __launch_bounds__(256,1) unlocks 255 regs.
// ---------------------------------------------------------------------------
#define R_BUF   (448 * 20)                // u32 per buffer
#define R_SMEM  (2 * R_BUF * 4)           // 71680 bytes dynamic

__global__ __launch_bounds__(256, 1) void gru_kernel(
    int t, const float* __restrict__ b_ih, const float* __restrict__ b_hh)
{
    extern __shared__ uint32_t smem[];

    int tid  = threadIdx.x;
    int lane = tid & 31, warp = tid >> 5;
    int g = lane >> 2, t4 = lane & 3;
    int m0 = blockIdx.y * 128;
    int j0 = blockIdx.x * 16;
    int rb = warp * 16;
    uint32_t sb = (uint32_t)__cvta_generic_to_shared(smem);

    // ---- per-thread global-load plan: 7 chunks of 16B ----
    const uint4* srcp[7];
    uint32_t     soff[7];                  // u32 offset within a buffer
#pragma unroll
    for (int i = 0; i < 7; i++) {
        int c = tid + i * 256;             // 0..1791
        if (c < 1024) {                    // A (h): hi then lo, 128 rows x 4 chunks
            int half = c >> 9, rem = c & 511;
            int row = rem >> 2, ch = rem & 3;
            const __nv_bfloat16* base =
                (half ? g_hs_lo : g_hs_hi) + (size_t)t * B_ * H_;
            srcp[i] = (const uint4*)base + (size_t)(m0 + row) * 128 + ch;
            soff[i] = half * 2560 + row * 20 + ch * 4;
        } else {                           // W: hi then lo, 96 rows x 4 chunks
            int c2 = c - 1024;
            int half = (c2 >= 384);
            int rem = half ? c2 - 384 : c2;
            int row = rem >> 2, ch = rem & 3;
            int gate = row >> 4, rj = row & 15;
            const __nv_bfloat16* base = half ? g_Wlo : g_Whi;
            srcp[i] = (const uint4*)base + (size_t)(gate * H_ + j0 + rj) * 128 + ch;
            soff[i] = 5120 + half * 1920 + row * 20 + ch * 4;
        }
    }

    // LDSM address bases (byte offsets within a buffer)
    uint32_t a_base = (uint32_t)((rb + (lane & 15)) * 80 + (lane >> 4) * 16);
    int q = lane >> 3;
    uint32_t b_base = (uint32_t)(20480 + (lane & 7) * 80 + (q >> 1) * 32 + (q & 1) * 16);

    float acc[6][2][4];
#pragma unroll
    for (int a = 0; a < 6; a++)
#pragma unroll
        for (int b = 0; b < 2; b++)
#pragma unroll
            for (int c = 0; c < 4; c++) acc[a][b][c] = 0.0f;

    uint4 pf[7];
    // Prologue: tile 0 -> regs -> buf 0
#pragma unroll
    for (int i = 0; i < 7; i++) pf[i] = srcp[i][0];
#pragma unroll
    for (int i = 0; i < 7; i++)
        *(uint4*)(smem + soff[i]) = pf[i];
    __syncthreads();

    for (int kt = 0; kt < 32; kt++) {
        // Prefetch next tile into registers (latency hidden under MMAs)
        if (kt + 1 < 32) {
#pragma unroll
            for (int i = 0; i < 7; i++) pf[i] = srcp[i][(kt + 1) * 4];
        }

        uint32_t bufB = sb + (uint32_t)(kt & 1) * (R_BUF * 4);

        // A fragments via LDSM.x4 (hi and lo, both k16 chunks)
        uint32_t ah[2][4], al[2][4];
#pragma unroll
        for (int kk = 0; kk < 2; kk++) {
            uint32_t aaddr = bufB + a_base + kk * 32;
            ldsm4(ah[kk][0], ah[kk][1], ah[kk][2], ah[kk][3], aaddr);
            ldsm4(al[kk][0], al[kk][1], al[kk][2], al[kk][3], aaddr + 10240);
        }

        // Two halves of 6 independent (gate,nf) chains each.
#pragma unroll
        for (int h = 0; h < 2; h++) {
            uint32_t bh[6][4], bl[6][4];
#pragma unroll
            for (int c = 0; c < 6; c++) {
                int gate = h * 3 + (c >> 1), nf = c & 1;
                uint32_t baddr = bufB + b_base + (uint32_t)((gate * 16 + nf * 8) * 80);
                ldsm4(bh[c][0], bh[c][1], bh[c][2], bh[c][3], baddr);
                ldsm4(bl[c][0], bl[c][1], bl[c][2], bl[c][3], baddr + 7680);
            }
            // 6 interleave passes; consecutive MMAs always hit different accs.
#pragma unroll
            for (int c = 0; c < 6; c++)
                mma_bf16(acc[h * 3 + (c >> 1)][c & 1],
                         ah[0][0], ah[0][1], ah[0][2], ah[0][3], bh[c][0], bh[c][1]);
#pragma unroll
            for (int c = 0; c < 6; c++)
                mma_bf16(acc[h * 3 + (c >> 1)][c & 1],
                         ah[1][0], ah[1][1], ah[1][2], ah[1][3], bh[c][2], bh[c][3]);
#pragma unroll
            for (int c = 0; c < 6; c++)
                mma_bf16(acc[h * 3 + (c >> 1)][c & 1],
                         ah[0][0], ah[0][1], ah[0][2], ah[0][3], bl[c][0], bl[c][1]);
#pragma unroll
            for (int c = 0; c < 6; c++)
                mma_bf16(acc[h * 3 + (c >> 1)][c & 1],
                         ah[1][0], ah[1][1], ah[1][2], ah[1][3], bl[c][2], bl[c][3]);
#pragma unroll
            for (int c = 0; c < 6; c++)
                mma_bf16(acc[h * 3 + (c >> 1)][c & 1],
                         al[0][0], al[0][1], al[0][2], al[0][3], bh[c][0], bh[c][1]);
#pragma unroll
            for (int c = 0; c < 6; c++)
                mma_bf16(acc[h * 3 + (c >> 1)][c & 1],
                         al[1][0], al[1][1], al[1][2], al[1][3], bh[c][2], bh[c][3]);
        }

        // Store prefetched tile into the other buffer
        if (kt + 1 < 32) {
            uint32_t* dst = smem + ((kt + 1) & 1) * R_BUF;
#pragma unroll
            for (int i = 0; i < 7; i++)
                *(uint4*)(dst + soff[i]) = pf[i];
        }
        __syncthreads();
    }

    // Epilogue: gate math + state update, split-write h_{t+1}.
    const __nv_bfloat16* src_hi = g_hs_hi + (size_t)t * B_ * H_;
    const __nv_bfloat16* src_lo = g_hs_lo + (size_t)t * B_ * H_;
    __nv_bfloat16* dst_hi = g_hs_hi + (size_t)(t + 1) * B_ * H_;
    __nv_bfloat16* dst_lo = g_hs_lo + (size_t)(t + 1) * B_ * H_;

#pragma unroll
    for (int nf = 0; nf < 2; nf++)
#pragma unroll
        for (int cc = 0; cc < 2; cc++) {
            int j = j0 + nf * 8 + 2 * t4 + cc;
            float bir = b_ih[j], biz = b_ih[H_ + j], bin = b_ih[2 * H_ + j];
            float bhr = b_hh[j], bhz = b_hh[H_ + j], bhn = b_hh[2 * H_ + j];
#pragma unroll
            for (int rr = 0; rr < 2; rr++) {
                int m  = m0 + warp * 16 + g + rr * 8;
                int ci = rr * 2 + cc;
                float ir  = acc[0][nf][ci] + bir;
                float iz  = acc[1][nf][ci] + biz;
                float inn = acc[2][nf][ci] + bin;
                float hr  = acc[3][nf][ci] + bhr;
                float hz  = acc[4][nf][ci] + bhz;
                float hn  = acc[5][nf][ci] + bhn;
                float r  = sigm(ir + hr);
                float z  = sigm(iz + hz);
                float nn = tanh_fast(inn + r * hn);
                size_t idx = (size_t)m * H_ + j;
                float hold = __bfloat162float(src_hi[idx]) + __bfloat162float(src_lo[idx]);
                float hnew = (1.0f - z) * nn + z * hold;
                __nv_bfloat16 hh = __float2bfloat16(hnew);
                dst_hi[idx] = hh;
                dst_lo[idx] = __float2bfloat16(hnew - __bfloat162float(hh));
            }
        }
}

// ---------------------------------------------------------------------------
// Host launcher: graph-capturable.
// ---------------------------------------------------------------------------
extern "C" void kernel_launch(void* const* d_in, const int* in_sizes, int n_in,
                              void* d_out, int out_size) {
    const float* x     = (const float*)d_in[0];
    const float* w1    = (const float*)d_in[1];
    const float* b1    = (const float*)d_in[2];
    const float* w2    = (const float*)d_in[3];
    const float* b2    = (const float*)d_in[4];
    const float* w_ih  = (const float*)d_in[5];
    const float* b_ih  = (const float*)d_in[6];
    const float* w_hh  = (const float*)d_in[7];
    const float* b_hh  = (const float*)d_in[8];
    const float* out_w = (const float*)d_in[9];
    const float* out_b = (const float*)d_in[10];
    float* out = (float*)d_out;

    int T = (out_size - B_ * H_) / (B_ * DOUT_);   // = 256
    if (T > T_) T = T_;

    static bool attr_done = false;
    if (!attr_done) {
        cudaFuncSetAttribute(gru_kernel,
                             cudaFuncAttributeMaxDynamicSharedMemorySize, R_SMEM);
        attr_done = true;
    }

    split_all_kernel<<<(SPLIT_TOTAL + 255) / 256, 256>>>(x, w1, w2, w_ih, w_hh, out_w);

    // FCN layer 1: t1 = x @ w1^T + b1
    gemm3_kernel<<<dim3(H_ / 64, B_ / 128), 256>>>(0, b1, nullptr, B_, H_, DIN_, 0);
    // FCN layer 2: latent -> d_out latent slice + hs slab 0
    gemm3_kernel<<<dim3(H_ / 64, B_ / 128), 256>>>(
        1, b2, out + (size_t)B_ * T * DOUT_, B_, H_, H_, 1);

    // GRU recurrence
    for (int t = 0; t < T; t++)
        gru_kernel<<<dim3(H_ / 16, B_ / 128), 256, R_SMEM>>>(t, b_ih, b_hh);

    // Output projection (permuted write)
    gemm3_kernel<<<dim3(DOUT_ / 64, (T * B_) / 128), 256>>>(
        2, out_b, out, T * B_, DOUT_, H_, 2);
}

// round 5
// speedup vs baseline: 1.4289x; 1.0297x over previous
#include <cuda_runtime.h>
#include <cuda_bf16.h>
#include <cstdint>
#include <cstddef>

// Problem constants (shapes fixed by the dataset).
#define B_    256
#define DIN_  512
#define H_    1024
#define DOUT_ 512
#define T_    256

// ---------------------------------------------------------------------------
// Device scratch. hs: T+1 slabs of [B, H] split bf16 (hi+lo).
// ---------------------------------------------------------------------------
__device__ __nv_bfloat16 g_hs_hi[(size_t)(T_ + 1) * B_ * H_];
__device__ __nv_bfloat16 g_hs_lo[(size_t)(T_ + 1) * B_ * H_];
__device__ __nv_bfloat16 g_Whi[6 * H_ * H_];   // rows: [w_ih(3H); w_hh(3H)] x H
__device__ __nv_bfloat16 g_Wlo[6 * H_ * H_];
__device__ __nv_bfloat16 g_xhi[B_ * DIN_],  g_xlo[B_ * DIN_];
__device__ __nv_bfloat16 g_w1hi[H_ * DIN_], g_w1lo[H_ * DIN_];
__device__ __nv_bfloat16 g_w2hi[H_ * H_],   g_w2lo[H_ * H_];
__device__ __nv_bfloat16 g_t1hi[B_ * H_],   g_t1lo[B_ * H_];
__device__ __nv_bfloat16 g_owhi[DOUT_ * H_], g_owlo[DOUT_ * H_];

// ---------------------------------------------------------------------------
// Fused split: all 6 fp32 tensors -> bf16 hi/lo in one launch.
// ---------------------------------------------------------------------------
#define SPLIT_TOTAL 8519680
__global__ void split_all_kernel(const float* __restrict__ x,
                                 const float* __restrict__ w1,
                                 const float* __restrict__ w2,
                                 const float* __restrict__ wih,
                                 const float* __restrict__ whh,
                                 const float* __restrict__ ow) {
    int i = blockIdx.x * blockDim.x + threadIdx.x;
    if (i >= SPLIT_TOTAL) return;
    const float* src;
    __nv_bfloat16 *hi, *lo;
    int off;
    if (i < 131072)        { src = x;   hi = g_xhi;  lo = g_xlo;  off = i; }
    else if (i < 655360)   { src = w1;  hi = g_w1hi; lo = g_w1lo; off = i - 131072; }
    else if (i < 1703936)  { src = w2;  hi = g_w2hi; lo = g_w2lo; off = i - 655360; }
    else if (i < 4849664)  { src = wih; hi = g_Whi;  lo = g_Wlo;  off = i - 1703936; }
    else if (i < 7995392)  { src = whh; hi = g_Whi + 3 * H_ * H_;
                             lo = g_Wlo + 3 * H_ * H_; off = i - 4849664; }
    else                   { src = ow;  hi = g_owhi; lo = g_owlo; off = i - 7995392; }
    float v = src[off];
    __nv_bfloat16 h = __float2bfloat16(v);
    hi[off] = h;
    lo[off] = __float2bfloat16(v - __bfloat162float(h));
}

// ---------------------------------------------------------------------------
// PTX helpers
// ---------------------------------------------------------------------------
__device__ __forceinline__ void mma_bf16(float* c,
                                         uint32_t a0, uint32_t a1, uint32_t a2, uint32_t a3,
                                         uint32_t b0, uint32_t b1) {
    asm volatile(
        "mma.sync.aligned.m16n8k16.row.col.f32.bf16.bf16.f32 "
        "{%0,%1,%2,%3}, {%4,%5,%6,%7}, {%8,%9}, {%0,%1,%2,%3};\n"
        : "+f"(c[0]), "+f"(c[1]), "+f"(c[2]), "+f"(c[3])
        : "r"(a0), "r"(a1), "r"(a2), "r"(a3), "r"(b0), "r"(b1));
}
__device__ __forceinline__ void ldsm4(uint32_t& r0, uint32_t& r1,
                                      uint32_t& r2, uint32_t& r3, uint32_t addr) {
    asm volatile("ldmatrix.sync.aligned.m8n8.x4.shared.b16 {%0,%1,%2,%3}, [%4];\n"
                 : "=r"(r0), "=r"(r1), "=r"(r2), "=r"(r3) : "r"(addr));
}
__device__ __forceinline__ float sigm(float x) { return 1.0f / (1.0f + __expf(-x)); }
__device__ __forceinline__ float tanh_fast(float x) {
    float a = fabsf(x);
    float e = __expf(-2.0f * a);
    return copysignf((1.0f - e) / (1.0f + e), x);
}

// ---------------------------------------------------------------------------
// Split-bf16 GEMM (unchanged, proven). BM=128, BN=64, BK=32; 256 threads.
// ---------------------------------------------------------------------------
__global__ __launch_bounds__(256, 2) void gemm3_kernel(
    int which, const float* __restrict__ bias, float* __restrict__ outf,
    int M, int N, int K, int mode)
{
    const __nv_bfloat16 *Ahi, *Alo, *Bhi, *Blo;
    if (which == 0)      { Ahi = g_xhi;  Alo = g_xlo;  Bhi = g_w1hi; Blo = g_w1lo; }
    else if (which == 1) { Ahi = g_t1hi; Alo = g_t1lo; Bhi = g_w2hi; Blo = g_w2lo; }
    else                 { Ahi = g_hs_hi + (size_t)B_ * H_; Alo = g_hs_lo + (size_t)B_ * H_;
                           Bhi = g_owhi; Blo = g_owlo; }
    const uint32_t* A32h = (const uint32_t*)Ahi;
    const uint32_t* A32l = (const uint32_t*)Alo;
    const uint32_t* B32h = (const uint32_t*)Bhi;
    const uint32_t* B32l = (const uint32_t*)Blo;

    __shared__ uint32_t sAh[128 * 20], sAl[128 * 20];
    __shared__ uint32_t sBh[64 * 20],  sBl[64 * 20];

    int tid  = threadIdx.x;
    int lane = tid & 31, warp = tid >> 5;
    int g = lane >> 2, t4 = lane & 3;
    int wm = warp >> 1, wn = warp & 1;
    int m0 = blockIdx.y * 128;
    int n0 = blockIdx.x * 64;
    int K2 = K >> 1;

    float acc[2][4][4];
#pragma unroll
    for (int a = 0; a < 2; a++)
#pragma unroll
        for (int b = 0; b < 4; b++)
#pragma unroll
            for (int c = 0; c < 4; c++) acc[a][b][c] = 0.0f;

    for (int k0 = 0; k0 < K; k0 += 32) {
        __syncthreads();
        int kc = k0 >> 1;
#pragma unroll
        for (int i = 0; i < 8; i++) {
            int e = tid + i * 256;
            int r = e >> 4, c = e & 15;
            size_t gi = (size_t)(m0 + r) * K2 + kc + c;
            sAh[r * 20 + c] = A32h[gi];
            sAl[r * 20 + c] = A32l[gi];
        }
#pragma unroll
        for (int i = 0; i < 4; i++) {
            int e = tid + i * 256;
            int r = e >> 4, c = e & 15;
            size_t gi = (size_t)(n0 + r) * K2 + kc + c;
            sBh[r * 20 + c] = B32h[gi];
            sBl[r * 20 + c] = B32l[gi];
        }
        __syncthreads();

#pragma unroll
        for (int kk = 0; kk < 2; kk++) {
            int base = kk * 8 + t4;
            uint32_t ah[2][4], al[2][4], bh[4][2], bl[4][2];
#pragma unroll
            for (int mf = 0; mf < 2; mf++) {
                int rb = wm * 32 + mf * 16;
                ah[mf][0] = sAh[(rb + g) * 20 + base];
                ah[mf][1] = sAh[(rb + g + 8) * 20 + base];
                ah[mf][2] = sAh[(rb + g) * 20 + base + 4];
                ah[mf][3] = sAh[(rb + g + 8) * 20 + base + 4];
                al[mf][0] = sAl[(rb + g) * 20 + base];
                al[mf][1] = sAl[(rb + g + 8) * 20 + base];
                al[mf][2] = sAl[(rb + g) * 20 + base + 4];
                al[mf][3] = sAl[(rb + g + 8) * 20 + base + 4];
            }
#pragma unroll
            for (int nf = 0; nf < 4; nf++) {
                int nb = wn * 32 + nf * 8 + g;
                bh[nf][0] = sBh[nb * 20 + base];
                bh[nf][1] = sBh[nb * 20 + base + 4];
                bl[nf][0] = sBl[nb * 20 + base];
                bl[nf][1] = sBl[nb * 20 + base + 4];
            }
#pragma unroll
            for (int mf = 0; mf < 2; mf++)
#pragma unroll
                for (int nf = 0; nf < 4; nf++)
                    mma_bf16(acc[mf][nf], ah[mf][0], ah[mf][1], ah[mf][2], ah[mf][3],
                             bh[nf][0], bh[nf][1]);
#pragma unroll
            for (int mf = 0; mf < 2; mf++)
#pragma unroll
                for (int nf = 0; nf < 4; nf++)
                    mma_bf16(acc[mf][nf], ah[mf][0], ah[mf][1], ah[mf][2], ah[mf][3],
                             bl[nf][0], bl[nf][1]);
#pragma unroll
            for (int mf = 0; mf < 2; mf++)
#pragma unroll
                for (int nf = 0; nf < 4; nf++)
                    mma_bf16(acc[mf][nf], al[mf][0], al[mf][1], al[mf][2], al[mf][3],
                             bh[nf][0], bh[nf][1]);
        }
    }

#pragma unroll
    for (int mf = 0; mf < 2; mf++)
#pragma unroll
        for (int nf = 0; nf < 4; nf++)
#pragma unroll
            for (int rr = 0; rr < 2; rr++)
#pragma unroll
                for (int cc = 0; cc < 2; cc++) {
                    int row = m0 + wm * 32 + mf * 16 + g + rr * 8;
                    int col = n0 + wn * 32 + nf * 8 + 2 * t4 + cc;
                    float v = acc[mf][nf][rr * 2 + cc] + bias[col];
                    if (mode == 0) {
                        __nv_bfloat16 h = __float2bfloat16(v);
                        g_t1hi[(size_t)row * N + col] = h;
                        g_t1lo[(size_t)row * N + col] =
                            __float2bfloat16(v - __bfloat162float(h));
                    } else if (mode == 1) {
                        outf[(size_t)row * N + col] = v;
                        __nv_bfloat16 h = __float2bfloat16(v);
                        g_hs_hi[(size_t)row * N + col] = h;
                        g_hs_lo[(size_t)row * N + col] =
                            __float2bfloat16(v - __bfloat162float(h));
                    } else {
                        int t = row >> 8;               // row = t*B + b
                        int b = row & 255;
                        int Trt = M >> 8;
                        outf[(size_t)b * Trt * N + (size_t)t * N + col] = v;
                    }
                }
}

// ---------------------------------------------------------------------------
// Fused GRU step, occupancy edition.
// BM=64, BN=16, grid (64 j, 4 m) = 256 CTAs -> 2 CTAs/SM -> 4 warps/SMSP.
// 8 warps: warp_m = warp&3 (16 rows each), warp_g = warp>>2 (i-gates 0-2 /
// h-gates 3-5). Smem buffer (u32, stride 20): Ah[64*20] Al[64*20] Bh[96*20]
// Bl[96*20] = 6400 u32; two buffers = 51200 B. 5 load chunks/thread.
// h-gate warps hand their accumulators to i-gate warps through smem at the
// end; i-gate warps do the gate math + state update.
// ---------------------------------------------------------------------------
#define R_BUF   (320 * 20)                // u32 per buffer (6400)
#define R_SMEM  (2 * R_BUF * 4)           // 51200 bytes dynamic

__global__ __launch_bounds__(256, 2) void gru_kernel(
    int t, const float* __restrict__ b_ih, const float* __restrict__ b_hh)
{
    extern __shared__ uint32_t smem[];

    int tid  = threadIdx.x;
    int lane = tid & 31, warp = tid >> 5;
    int g = lane >> 2, t4 = lane & 3;
    int warp_m = warp & 3, warp_g = warp >> 2;
    int m0 = blockIdx.y * 64;
    int j0 = blockIdx.x * 16;
    uint32_t sb = (uint32_t)__cvta_generic_to_shared(smem);

    // ---- per-thread global-load plan: 5 chunks of 16B ----
    const uint4* srcp[5];
    uint32_t     soff[5];                  // u32 offset within a buffer
#pragma unroll
    for (int i = 0; i < 5; i++) {
        int c = tid + i * 256;             // 0..1279
        if (c < 512) {                     // A (h): hi then lo, 64 rows x 4 chunks
            int half = c >> 8, rem = c & 255;
            int row = rem >> 2, ch = rem & 3;
            const __nv_bfloat16* base =
                (half ? g_hs_lo : g_hs_hi) + (size_t)t * B_ * H_;
            srcp[i] = (const uint4*)base + (size_t)(m0 + row) * 128 + ch;
            soff[i] = half * 1280 + row * 20 + ch * 4;
        } else {                           // W: hi then lo, 96 rows x 4 chunks
            int c2 = c - 512;              // 0..767
            int half = (c2 >= 384);
            int rem = half ? c2 - 384 : c2;
            int row = rem >> 2, ch = rem & 3;
            int gate = row >> 4, rj = row & 15;
            const __nv_bfloat16* base = half ? g_Wlo : g_Whi;
            srcp[i] = (const uint4*)base + (size_t)(gate * H_ + j0 + rj) * 128 + ch;
            soff[i] = 2560 + half * 1920 + row * 20 + ch * 4;
        }
    }

    // LDSM address bases (byte offsets within a buffer)
    int rb = warp_m * 16;
    uint32_t a_base = (uint32_t)((rb + (lane & 15)) * 80 + (lane >> 4) * 16);
    int q = lane >> 3;
    uint32_t b_base = (uint32_t)(10240 + (lane & 7) * 80 + (q >> 1) * 32 + (q & 1) * 16);

    float acc[3][2][4];
#pragma unroll
    for (int a = 0; a < 3; a++)
#pragma unroll
        for (int b = 0; b < 2; b++)
#pragma unroll
            for (int c = 0; c < 4; c++) acc[a][b][c] = 0.0f;

    uint4 pf[5];
#pragma unroll
    for (int i = 0; i < 5; i++) pf[i] = srcp[i][0];
#pragma unroll
    for (int i = 0; i < 5; i++)
        *(uint4*)(smem + soff[i]) = pf[i];
    __syncthreads();

    for (int kt = 0; kt < 32; kt++) {
        if (kt + 1 < 32) {
#pragma unroll
            for (int i = 0; i < 5; i++) pf[i] = srcp[i][(kt + 1) * 4];
        }

        uint32_t bufB = sb + (uint32_t)(kt & 1) * (R_BUF * 4);

        // A fragments via LDSM.x4 (hi and lo, both k16 chunks); Al at +5120B
        uint32_t ah[2][4], al[2][4];
#pragma unroll
        for (int kk = 0; kk < 2; kk++) {
            uint32_t aaddr = bufB + a_base + kk * 32;
            ldsm4(ah[kk][0], ah[kk][1], ah[kk][2], ah[kk][3], aaddr);
            ldsm4(al[kk][0], al[kk][1], al[kk][2], al[kk][3], aaddr + 5120);
        }

        // 3 gates for this warp's gate-group; interleave the 2 nf chains.
#pragma unroll
        for (int gi = 0; gi < 3; gi++) {
            int gate = warp_g * 3 + gi;
            uint32_t baddr = bufB + b_base + (uint32_t)((gate * 16) * 80);
            uint32_t bh0[4], bl0[4], bh1[4], bl1[4];
            ldsm4(bh0[0], bh0[1], bh0[2], bh0[3], baddr);
            ldsm4(bl0[0], bl0[1], bl0[2], bl0[3], baddr + 7680);
            ldsm4(bh1[0], bh1[1], bh1[2], bh1[3], baddr + 640);
            ldsm4(bl1[0], bl1[1], bl1[2], bl1[3], baddr + 640 + 7680);
            mma_bf16(acc[gi][0], ah[0][0], ah[0][1], ah[0][2], ah[0][3], bh0[0], bh0[1]);
            mma_bf16(acc[gi][1], ah[0][0], ah[0][1], ah[0][2], ah[0][3], bh1[0], bh1[1]);
            mma_bf16(acc[gi][0], ah[1][0], ah[1][1], ah[1][2], ah[1][3], bh0[2], bh0[3]);
            mma_bf16(acc[gi][1], ah[1][0], ah[1][1], ah[1][2], ah[1][3], bh1[2], bh1[3]);
            mma_bf16(acc[gi][0], ah[0][0], ah[0][1], ah[0][2], ah[0][3], bl0[0], bl0[1]);
            mma_bf16(acc[gi][1], ah[0][0], ah[0][1], ah[0][2], ah[0][3], bl1[0], bl1[1]);
            mma_bf16(acc[gi][0], ah[1][0], ah[1][1], ah[1][2], ah[1][3], bl0[2], bl0[3]);
            mma_bf16(acc[gi][1], ah[1][0], ah[1][1], ah[1][2], ah[1][3], bl1[2], bl1[3]);
            mma_bf16(acc[gi][0], al[0][0], al[0][1], al[0][2], al[0][3], bh0[0], bh0[1]);
            mma_bf16(acc[gi][1], al[0][0], al[0][1], al[0][2], al[0][3], bh1[0], bh1[1]);
            mma_bf16(acc[gi][0], al[1][0], al[1][1], al[1][2], al[1][3], bh0[2], bh0[3]);
            mma_bf16(acc[gi][1], al[1][0], al[1][1], al[1][2], al[1][3], bh1[2], bh1[3]);
        }

        if (kt + 1 < 32) {
            uint32_t* dst = smem + ((kt + 1) & 1) * R_BUF;
#pragma unroll
            for (int i = 0; i < 5; i++)
                *(uint4*)(dst + soff[i]) = pf[i];
        }
        __syncthreads();
    }

    // ---- gate exchange: h-gate warps -> smem -> i-gate warps ----
    float* xch = (float*)smem;             // 4*32*24 floats = 12 KB, buffers dead
    if (warp_g == 1) {
        int base = (warp_m * 32 + lane) * 24;
#pragma unroll
        for (int a = 0; a < 3; a++)
#pragma unroll
            for (int b = 0; b < 2; b++)
#pragma unroll
                for (int c = 0; c < 4; c++)
                    xch[base + a * 8 + b * 4 + c] = acc[a][b][c];
    }
    __syncthreads();

    if (warp_g == 0) {
        int base = (warp_m * 32 + lane) * 24;
        const __nv_bfloat16* src_hi = g_hs_hi + (size_t)t * B_ * H_;
        const __nv_bfloat16* src_lo = g_hs_lo + (size_t)t * B_ * H_;
        __nv_bfloat16* dst_hi = g_hs_hi + (size_t)(t + 1) * B_ * H_;
        __nv_bfloat16* dst_lo = g_hs_lo + (size_t)(t + 1) * B_ * H_;

#pragma unroll
        for (int nf = 0; nf < 2; nf++)
#pragma unroll
            for (int cc = 0; cc < 2; cc++) {
                int j = j0 + nf * 8 + 2 * t4 + cc;
                float bir = b_ih[j], biz = b_ih[H_ + j], bin = b_ih[2 * H_ + j];
                float bhr = b_hh[j], bhz = b_hh[H_ + j], bhn = b_hh[2 * H_ + j];
#pragma unroll
                for (int rr = 0; rr < 2; rr++) {
                    int m  = m0 + warp_m * 16 + g + rr * 8;
                    int ci = rr * 2 + cc;
                    float ir  = acc[0][nf][ci] + bir;
                    float iz  = acc[1][nf][ci] + biz;
                    float inn = acc[2][nf][ci] + bin;
                    float hr  = xch[base + 0 * 8 + nf * 4 + ci] + bhr;
                    float hz  = xch[base + 1 * 8 + nf * 4 + ci] + bhz;
                    float hn  = xch[base + 2 * 8 + nf * 4 + ci] + bhn;
                    float r  = sigm(ir + hr);
                    float z  = sigm(iz + hz);
                    float nn = tanh_fast(inn + r * hn);
                    size_t idx = (size_t)m * H_ + j;
                    float hold = __bfloat162float(src_hi[idx]) + __bfloat162float(src_lo[idx]);
                    float hnew = (1.0f - z) * nn + z * hold;
                    __nv_bfloat16 hh = __float2bfloat16(hnew);
                    dst_hi[idx] = hh;
                    dst_lo[idx] = __float2bfloat16(hnew - __bfloat162float(hh));
                }
            }
    }
}

// ---------------------------------------------------------------------------
// Host launcher: graph-capturable.
// ---------------------------------------------------------------------------
extern "C" void kernel_launch(void* const* d_in, const int* in_sizes, int n_in,
                              void* d_out, int out_size) {
    const float* x     = (const float*)d_in[0];
    const float* w1    = (const float*)d_in[1];
    const float* b1    = (const float*)d_in[2];
    const float* w2    = (const float*)d_in[3];
    const float* b2    = (const float*)d_in[4];
    const float* w_ih  = (const float*)d_in[5];
    const float* b_ih  = (const float*)d_in[6];
    const float* w_hh  = (const float*)d_in[7];
    const float* b_hh  = (const float*)d_in[8];
    const float* out_w = (const float*)d_in[9];
    const float* out_b = (const float*)d_in[10];
    float* out = (float*)d_out;

    int T = (out_size - B_ * H_) / (B_ * DOUT_);   // = 256
    if (T > T_) T = T_;

    static bool attr_done = false;
    if (!attr_done) {
        cudaFuncSetAttribute(gru_kernel,
                             cudaFuncAttributeMaxDynamicSharedMemorySize, R_SMEM);
        attr_done = true;
    }

    split_all_kernel<<<(SPLIT_TOTAL + 255) / 256, 256>>>(x, w1, w2, w_ih, w_hh, out_w);

    // FCN layer 1: t1 = x @ w1^T + b1
    gemm3_kernel<<<dim3(H_ / 64, B_ / 128), 256>>>(0, b1, nullptr, B_, H_, DIN_, 0);
    // FCN layer 2: latent -> d_out latent slice + hs slab 0
    gemm3_kernel<<<dim3(H_ / 64, B_ / 128), 256>>>(
        1, b2, out + (size_t)B_ * T * DOUT_, B_, H_, H_, 1);

    // GRU recurrence (BM=64 x BN=16, 256 CTAs)
    for (int t = 0; t < T; t++)
        gru_kernel<<<dim3(H_ / 16, B_ / 64), 256, R_SMEM>>>(t, b_ih, b_hh);

    // Output projection (permuted write)
    gemm3_kernel<<<dim3(DOUT_ / 64, (T * B_) / 128), 256>>>(
        2, out_b, out, T * B_, DOUT_, H_, 2);
}

// round 9
// speedup vs baseline: 1.5914x; 1.1137x over previous
#include <cuda_runtime.h>
#include <cuda_bf16.h>
#include <cstdint>
#include <cstddef>

// Problem constants (shapes fixed by the dataset).
#define B_    256
#define DIN_  512
#define H_    1024
#define DOUT_ 512
#define T_    256

// ---------------------------------------------------------------------------
// Device scratch. hs: T+1 slabs of [B, H] split bf16 (hi+lo).
// ---------------------------------------------------------------------------
__device__ __nv_bfloat16 g_hs_hi[(size_t)(T_ + 1) * B_ * H_];
__device__ __nv_bfloat16 g_hs_lo[(size_t)(T_ + 1) * B_ * H_];
__device__ __nv_bfloat16 g_Whi[6 * H_ * H_];   // rows: [w_ih(3H); w_hh(3H)] x H
__device__ __nv_bfloat16 g_Wlo[6 * H_ * H_];
__device__ __nv_bfloat16 g_xhi[B_ * DIN_],  g_xlo[B_ * DIN_];
__device__ __nv_bfloat16 g_w1hi[H_ * DIN_], g_w1lo[H_ * DIN_];
__device__ __nv_bfloat16 g_w2hi[H_ * H_],   g_w2lo[H_ * H_];
__device__ __nv_bfloat16 g_t1hi[B_ * H_],   g_t1lo[B_ * H_];
__device__ __nv_bfloat16 g_owhi[DOUT_ * H_], g_owlo[DOUT_ * H_];

// ---------------------------------------------------------------------------
// Fused split: all 6 fp32 tensors -> bf16 hi/lo in one launch.
// ---------------------------------------------------------------------------
#define SPLIT_TOTAL 8519680
__global__ void split_all_kernel(const float* __restrict__ x,
                                 const float* __restrict__ w1,
                                 const float* __restrict__ w2,
                                 const float* __restrict__ wih,
                                 const float* __restrict__ whh,
                                 const float* __restrict__ ow) {
    int i = blockIdx.x * blockDim.x + threadIdx.x;
    if (i >= SPLIT_TOTAL) return;
    const float* src;
    __nv_bfloat16 *hi, *lo;
    int off;
    if (i < 131072)        { src = x;   hi = g_xhi;  lo = g_xlo;  off = i; }
    else if (i < 655360)   { src = w1;  hi = g_w1hi; lo = g_w1lo; off = i - 131072; }
    else if (i < 1703936)  { src = w2;  hi = g_w2hi; lo = g_w2lo; off = i - 655360; }
    else if (i < 4849664)  { src = wih; hi = g_Whi;  lo = g_Wlo;  off = i - 1703936; }
    else if (i < 7995392)  { src = whh; hi = g_Whi + 3 * H_ * H_;
                             lo = g_Wlo + 3 * H_ * H_; off = i - 4849664; }
    else                   { src = ow;  hi = g_owhi; lo = g_owlo; off = i - 7995392; }
    float v = src[off];
    __nv_bfloat16 h = __float2bfloat16(v);
    hi[off] = h;
    lo[off] = __float2bfloat16(v - __bfloat162float(h));
}

// ---------------------------------------------------------------------------
// PTX helpers
// ---------------------------------------------------------------------------
__device__ __forceinline__ void mma_bf16(float* c,
                                         uint32_t a0, uint32_t a1, uint32_t a2, uint32_t a3,
                                         uint32_t b0, uint32_t b1) {
    asm volatile(
        "mma.sync.aligned.m16n8k16.row.col.f32.bf16.bf16.f32 "
        "{%0,%1,%2,%3}, {%4,%5,%6,%7}, {%8,%9}, {%0,%1,%2,%3};\n"
        : "+f"(c[0]), "+f"(c[1]), "+f"(c[2]), "+f"(c[3])
        : "r"(a0), "r"(a1), "r"(a2), "r"(a3), "r"(b0), "r"(b1));
}
__device__ __forceinline__ void ldsm4(uint32_t& r0, uint32_t& r1,
                                      uint32_t& r2, uint32_t& r3, uint32_t addr) {
    asm volatile("ldmatrix.sync.aligned.m8n8.x4.shared.b16 {%0,%1,%2,%3}, [%4];\n"
                 : "=r"(r0), "=r"(r1), "=r"(r2), "=r"(r3) : "r"(addr));
}
__device__ __forceinline__ void cp16(uint32_t dst, const void* src) {
    asm volatile("cp.async.cg.shared.global [%0], [%1], 16;\n" :: "r"(dst), "l"(src));
}
__device__ __forceinline__ void cp_commit() {
    asm volatile("cp.async.commit_group;\n");
}
template <int N>
__device__ __forceinline__ void cp_wait() {
    asm volatile("cp.async.wait_group %0;\n" :: "n"(N));
}
__device__ __forceinline__ float sigm(float x) { return 1.0f / (1.0f + __expf(-x)); }
__device__ __forceinline__ float tanh_fast(float x) {
    float a = fabsf(x);
    float e = __expf(-2.0f * a);
    return copysignf((1.0f - e) / (1.0f + e), x);
}

// ---------------------------------------------------------------------------
// Split-bf16 GEMM (proven r5 version). BM=128, BN=64, BK=32; 256 threads.
// ---------------------------------------------------------------------------
__global__ __launch_bounds__(256, 2) void gemm3_kernel(
    int which, const float* __restrict__ bias, float* __restrict__ outf,
    int M, int N, int K, int mode)
{
    const __nv_bfloat16 *Ahi, *Alo, *Bhi, *Blo;
    if (which == 0)      { Ahi = g_xhi;  Alo = g_xlo;  Bhi = g_w1hi; Blo = g_w1lo; }
    else if (which == 1) { Ahi = g_t1hi; Alo = g_t1lo; Bhi = g_w2hi; Blo = g_w2lo; }
    else                 { Ahi = g_hs_hi + (size_t)B_ * H_; Alo = g_hs_lo + (size_t)B_ * H_;
                           Bhi = g_owhi; Blo = g_owlo; }
    const uint32_t* A32h = (const uint32_t*)Ahi;
    const uint32_t* A32l = (const uint32_t*)Alo;
    const uint32_t* B32h = (const uint32_t*)Bhi;
    const uint32_t* B32l = (const uint32_t*)Blo;

    __shared__ uint32_t sAh[128 * 20], sAl[128 * 20];
    __shared__ uint32_t sBh[64 * 20],  sBl[64 * 20];

    int tid  = threadIdx.x;
    int lane = tid & 31, warp = tid >> 5;
    int g = lane >> 2, t4 = lane & 3;
    int wm = warp >> 1, wn = warp & 1;
    int m0 = blockIdx.y * 128;
    int n0 = blockIdx.x * 64;
    int K2 = K >> 1;

    float acc[2][4][4];
#pragma unroll
    for (int a = 0; a < 2; a++)
#pragma unroll
        for (int b = 0; b < 4; b++)
#pragma unroll
            for (int c = 0; c < 4; c++) acc[a][b][c] = 0.0f;

    for (int k0 = 0; k0 < K; k0 += 32) {
        __syncthreads();
        int kc = k0 >> 1;
#pragma unroll
        for (int i = 0; i < 8; i++) {
            int e = tid + i * 256;
            int r = e >> 4, c = e & 15;
            size_t gi = (size_t)(m0 + r) * K2 + kc + c;
            sAh[r * 20 + c] = A32h[gi];
            sAl[r * 20 + c] = A32l[gi];
        }
#pragma unroll
        for (int i = 0; i < 4; i++) {
            int e = tid + i * 256;
            int r = e >> 4, c = e & 15;
            size_t gi = (size_t)(n0 + r) * K2 + kc + c;
            sBh[r * 20 + c] = B32h[gi];
            sBl[r * 20 + c] = B32l[gi];
        }
        __syncthreads();

#pragma unroll
        for (int kk = 0; kk < 2; kk++) {
            int base = kk * 8 + t4;
            uint32_t ah[2][4], al[2][4], bh[4][2], bl[4][2];
#pragma unroll
            for (int mf = 0; mf < 2; mf++) {
                int rb = wm * 32 + mf * 16;
                ah[mf][0] = sAh[(rb + g) * 20 + base];
                ah[mf][1] = sAh[(rb + g + 8) * 20 + base];
                ah[mf][2] = sAh[(rb + g) * 20 + base + 4];
                ah[mf][3] = sAh[(rb + g + 8) * 20 + base + 4];
                al[mf][0] = sAl[(rb + g) * 20 + base];
                al[mf][1] = sAl[(rb + g + 8) * 20 + base];
                al[mf][2] = sAl[(rb + g) * 20 + base + 4];
                al[mf][3] = sAl[(rb + g + 8) * 20 + base + 4];
            }
#pragma unroll
            for (int nf = 0; nf < 4; nf++) {
                int nb = wn * 32 + nf * 8 + g;
                bh[nf][0] = sBh[nb * 20 + base];
                bh[nf][1] = sBh[nb * 20 + base + 4];
                bl[nf][0] = sBl[nb * 20 + base];
                bl[nf][1] = sBl[nb * 20 + base + 4];
            }
#pragma unroll
            for (int mf = 0; mf < 2; mf++)
#pragma unroll
                for (int nf = 0; nf < 4; nf++)
                    mma_bf16(acc[mf][nf], ah[mf][0], ah[mf][1], ah[mf][2], ah[mf][3],
                             bh[nf][0], bh[nf][1]);
#pragma unroll
            for (int mf = 0; mf < 2; mf++)
#pragma unroll
                for (int nf = 0; nf < 4; nf++)
                    mma_bf16(acc[mf][nf], ah[mf][0], ah[mf][1], ah[mf][2], ah[mf][3],
                             bl[nf][0], bl[nf][1]);
#pragma unroll
            for (int mf = 0; mf < 2; mf++)
#pragma unroll
                for (int nf = 0; nf < 4; nf++)
                    mma_bf16(acc[mf][nf], al[mf][0], al[mf][1], al[mf][2], al[mf][3],
                             bh[nf][0], bh[nf][1]);
        }
    }

#pragma unroll
    for (int mf = 0; mf < 2; mf++)
#pragma unroll
        for (int nf = 0; nf < 4; nf++)
#pragma unroll
            for (int rr = 0; rr < 2; rr++)
#pragma unroll
                for (int cc = 0; cc < 2; cc++) {
                    int row = m0 + wm * 32 + mf * 16 + g + rr * 8;
                    int col = n0 + wn * 32 + nf * 8 + 2 * t4 + cc;
                    float v = acc[mf][nf][rr * 2 + cc] + bias[col];
                    if (mode == 0) {
                        __nv_bfloat16 h = __float2bfloat16(v);
                        g_t1hi[(size_t)row * N + col] = h;
                        g_t1lo[(size_t)row * N + col] =
                            __float2bfloat16(v - __bfloat162float(h));
                    } else if (mode == 1) {
                        outf[(size_t)row * N + col] = v;
                        __nv_bfloat16 h = __float2bfloat16(v);
                        g_hs_hi[(size_t)row * N + col] = h;
                        g_hs_lo[(size_t)row * N + col] =
                            __float2bfloat16(v - __bfloat162float(h));
                    } else {
                        int t = row >> 8;               // row = t*B + b
                        int b = row & 255;
                        int Trt = M >> 8;
                        outf[(size_t)b * Trt * N + (size_t)t * N + col] = v;
                    }
                }
}

// ---------------------------------------------------------------------------
// Fused GRU step — r5 math, 4-stage cp.async pipeline load path.
// BM=64, BN=16, grid (64 j, 4 m) = 256 CTAs, 2 CTAs/SM.
// 8 warps: warp_m = warp&3 (16 rows), warp_g = warp>>2 (i-gates / h-gates).
// Stage (u32, stride 20): Ah[64*20] Al[64*20] Bh[96*20] Bl[96*20] = 6400 u32.
// Per tile: wait_group 2 -> ONE sync -> issue stage kt+3 -> compute stage kt.
// ---------------------------------------------------------------------------
#define STAGES  4
#define R_BUF   (320 * 20)                 // u32 per stage (6400)
#define R_SMEM  (STAGES * R_BUF * 4)       // 102400 bytes dynamic

__global__ __launch_bounds__(256, 2) void gru_kernel(
    int t, const float* __restrict__ b_ih, const float* __restrict__ b_hh)
{
    extern __shared__ uint32_t smem[];

    int tid  = threadIdx.x;
    int lane = tid & 31, warp = tid >> 5;
    int g = lane >> 2, t4 = lane & 3;
    int warp_m = warp & 3, warp_g = warp >> 2;
    int m0 = blockIdx.y * 64;
    int j0 = blockIdx.x * 16;
    uint32_t sb = (uint32_t)__cvta_generic_to_shared(smem);

    // ---- per-thread load plan: 5 x 16B chunks per k32 tile ----
    const uint4* srcp[5];
    uint32_t     soff[5];                  // byte offset within a stage
#pragma unroll
    for (int i = 0; i < 5; i++) {
        int c = tid + i * 256;             // 0..1279
        if (c < 512) {                     // A (h): hi then lo, 64 rows x 4 chunks
            int half = c >> 8, rem = c & 255;
            int row = rem >> 2, ch = rem & 3;
            const __nv_bfloat16* base =
                (half ? g_hs_lo : g_hs_hi) + (size_t)t * B_ * H_;
            srcp[i] = (const uint4*)base + (size_t)(m0 + row) * 128 + ch;
            soff[i] = (uint32_t)(half * 1280 + row * 20 + ch * 4) * 4;
        } else {                           // W: hi then lo, 96 rows x 4 chunks
            int c2 = c - 512;              // 0..767
            int half = (c2 >= 384);
            int rem = half ? c2 - 384 : c2;
            int row = rem >> 2, ch = rem & 3;
            int gate = row >> 4, rj = row & 15;
            const __nv_bfloat16* base = half ? g_Wlo : g_Whi;
            srcp[i] = (const uint4*)base + (size_t)(gate * H_ + j0 + rj) * 128 + ch;
            soff[i] = (uint32_t)(2560 + half * 1920 + row * 20 + ch * 4) * 4;
        }
    }

    // LDSM address bases (byte offsets within a stage)
    int rb = warp_m * 16;
    uint32_t a_base = (uint32_t)((rb + (lane & 15)) * 80 + (lane >> 4) * 16);
    int q = lane >> 3;
    uint32_t b_base = (uint32_t)(10240 + (lane & 7) * 80 + (q >> 1) * 32 + (q & 1) * 16);

    float acc[3][2][4];
#pragma unroll
    for (int a = 0; a < 3; a++)
#pragma unroll
        for (int b = 0; b < 2; b++)
#pragma unroll
            for (int c = 0; c < 4; c++) acc[a][b][c] = 0.0f;

    // ---- async loader: tile kt -> stage kt & 3 ----
    auto load_tile = [&](int kt) {
        if (kt < 32) {
            uint32_t sbase = sb + (uint32_t)(kt & (STAGES - 1)) * (R_BUF * 4);
#pragma unroll
            for (int i = 0; i < 5; i++)
                cp16(sbase + soff[i], srcp[i] + kt * 4);
        }
        cp_commit();
    };

    // Prologue: stages 0..2 in flight
    load_tile(0);
    load_tile(1);
    load_tile(2);

    for (int kt = 0; kt < 32; kt++) {
        cp_wait<2>();                      // tile kt resident
        __syncthreads();                   // all warps done reading stage (kt-1)&3
        load_tile(kt + 3);                 // refill the stage freed by kt-1

        uint32_t bufB = sb + (uint32_t)(kt & (STAGES - 1)) * (R_BUF * 4);

        // A fragments via LDSM.x4 (hi and lo, both k16 chunks); Al at +5120B
        uint32_t ah[2][4], al[2][4];
#pragma unroll
        for (int kk = 0; kk < 2; kk++) {
            uint32_t aaddr = bufB + a_base + kk * 32;
            ldsm4(ah[kk][0], ah[kk][1], ah[kk][2], ah[kk][3], aaddr);
            ldsm4(al[kk][0], al[kk][1], al[kk][2], al[kk][3], aaddr + 5120);
        }

        // 3 gates for this warp's gate-group; interleave the 2 nf chains.
#pragma unroll
        for (int gi = 0; gi < 3; gi++) {
            int gate = warp_g * 3 + gi;
            uint32_t baddr = bufB + b_base + (uint32_t)((gate * 16) * 80);
            uint32_t bh0[4], bl0[4], bh1[4], bl1[4];
            ldsm4(bh0[0], bh0[1], bh0[2], bh0[3], baddr);
            ldsm4(bl0[0], bl0[1], bl0[2], bl0[3], baddr + 7680);
            ldsm4(bh1[0], bh1[1], bh1[2], bh1[3], baddr + 640);
            ldsm4(bl1[0], bl1[1], bl1[2], bl1[3], baddr + 640 + 7680);
            mma_bf16(acc[gi][0], ah[0][0], ah[0][1], ah[0][2], ah[0][3], bh0[0], bh0[1]);
            mma_bf16(acc[gi][1], ah[0][0], ah[0][1], ah[0][2], ah[0][3], bh1[0], bh1[1]);
            mma_bf16(acc[gi][0], ah[1][0], ah[1][1], ah[1][2], ah[1][3], bh0[2], bh0[3]);
            mma_bf16(acc[gi][1], ah[1][0], ah[1][1], ah[1][2], ah[1][3], bh1[2], bh1[3]);
            mma_bf16(acc[gi][0], ah[0][0], ah[0][1], ah[0][2], ah[0][3], bl0[0], bl0[1]);
            mma_bf16(acc[gi][1], ah[0][0], ah[0][1], ah[0][2], ah[0][3], bl1[0], bl1[1]);
            mma_bf16(acc[gi][0], ah[1][0], ah[1][1], ah[1][2], ah[1][3], bl0[2], bl0[3]);
            mma_bf16(acc[gi][1], ah[1][0], ah[1][1], ah[1][2], ah[1][3], bl1[2], bl1[3]);
            mma_bf16(acc[gi][0], al[0][0], al[0][1], al[0][2], al[0][3], bh0[0], bh0[1]);
            mma_bf16(acc[gi][1], al[0][0], al[0][1], al[0][2], al[0][3], bh1[0], bh1[1]);
            mma_bf16(acc[gi][0], al[1][0], al[1][1], al[1][2], al[1][3], bh0[2], bh0[3]);
            mma_bf16(acc[gi][1], al[1][0], al[1][1], al[1][2], al[1][3], bh1[2], bh1[3]);
        }
    }

    cp_wait<0>();
    __syncthreads();

    // ---- gate exchange: h-gate warps -> smem -> i-gate warps ----
    float* xch = (float*)smem;             // 4*32*24 floats = 12 KB (stages dead)
    if (warp_g == 1) {
        int base = (warp_m * 32 + lane) * 24;
#pragma unroll
        for (int a = 0; a < 3; a++)
#pragma unroll
            for (int b = 0; b < 2; b++)
#pragma unroll
                for (int c = 0; c < 4; c++)
                    xch[base + a * 8 + b * 4 + c] = acc[a][b][c];
    }
    __syncthreads();

    if (warp_g == 0) {
        int base = (warp_m * 32 + lane) * 24;
        const __nv_bfloat16* src_hi = g_hs_hi + (size_t)t * B_ * H_;
        const __nv_bfloat16* src_lo = g_hs_lo + (size_t)t * B_ * H_;
        __nv_bfloat16* dst_hi = g_hs_hi + (size_t)(t + 1) * B_ * H_;
        __nv_bfloat16* dst_lo = g_hs_lo + (size_t)(t + 1) * B_ * H_;

#pragma unroll
        for (int nf = 0; nf < 2; nf++)
#pragma unroll
            for (int cc = 0; cc < 2; cc++) {
                int j = j0 + nf * 8 + 2 * t4 + cc;
                float bir = b_ih[j], biz = b_ih[H_ + j], bin = b_ih[2 * H_ + j];
                float bhr = b_hh[j], bhz = b_hh[H_ + j], bhn = b_hh[2 * H_ + j];
#pragma unroll
                for (int rr = 0; rr < 2; rr++) {
                    int m  = m0 + warp_m * 16 + g + rr * 8;
                    int ci = rr * 2 + cc;
                    float ir  = acc[0][nf][ci] + bir;
                    float iz  = acc[1][nf][ci] + biz;
                    float inn = acc[2][nf][ci] + bin;
                    float hr  = xch[base + 0 * 8 + nf * 4 + ci] + bhr;
                    float hz  = xch[base + 1 * 8 + nf * 4 + ci] + bhz;
                    float hn  = xch[base + 2 * 8 + nf * 4 + ci] + bhn;
                    float r  = sigm(ir + hr);
                    float z  = sigm(iz + hz);
                    float nn = tanh_fast(inn + r * hn);
                    size_t idx = (size_t)m * H_ + j;
                    float hold = __bfloat162float(src_hi[idx]) + __bfloat162float(src_lo[idx]);
                    float hnew = (1.0f - z) * nn + z * hold;
                    __nv_bfloat16 hh = __float2bfloat16(hnew);
                    dst_hi[idx] = hh;
                    dst_lo[idx] = __float2bfloat16(hnew - __bfloat162float(hh));
                }
            }
    }
}

// ---------------------------------------------------------------------------
// Host launcher: graph-capturable.
// ---------------------------------------------------------------------------
extern "C" void kernel_launch(void* const* d_in, const int* in_sizes, int n_in,
                              void* d_out, int out_size) {
    const float* x     = (const float*)d_in[0];
    const float* w1    = (const float*)d_in[1];
    const float* b1    = (const float*)d_in[2];
    const float* w2    = (const float*)d_in[3];
    const float* b2    = (const float*)d_in[4];
    const float* w_ih  = (const float*)d_in[5];
    const float* b_ih  = (const float*)d_in[6];
    const float* w_hh  = (const float*)d_in[7];
    const float* b_hh  = (const float*)d_in[8];
    const float* out_w = (const float*)d_in[9];
    const float* out_b = (const float*)d_in[10];
    float* out = (float*)d_out;

    int T = (out_size - B_ * H_) / (B_ * DOUT_);   // = 256
    if (T > T_) T = T_;

    static bool attr_done = false;
    if (!attr_done) {
        cudaFuncSetAttribute(gru_kernel,
                             cudaFuncAttributeMaxDynamicSharedMemorySize, R_SMEM);
        attr_done = true;
    }

    split_all_kernel<<<(SPLIT_TOTAL + 255) / 256, 256>>>(x, w1, w2, w_ih, w_hh, out_w);

    // FCN layer 1: t1 = x @ w1^T + b1
    gemm3_kernel<<<dim3(H_ / 64, B_ / 128), 256>>>(0, b1, nullptr, B_, H_, DIN_, 0);
    // FCN layer 2: latent -> d_out latent slice + hs slab 0
    gemm3_kernel<<<dim3(H_ / 64, B_ / 128), 256>>>(
        1, b2, out + (size_t)B_ * T * DOUT_, B_, H_, H_, 1);

    // GRU recurrence (BM=64 x BN=16, 256 CTAs, cp.async 4-stage)
    for (int t = 0; t < T; t++)
        gru_kernel<<<dim3(H_ / 16, B_ / 64), 256, R_SMEM>>>(t, b_ih, b_hh);

    // Output projection (permuted write)
    gemm3_kernel<<<dim3(DOUT_ / 64, (T * B_) / 128), 256>>>(
        2, out_b, out, T * B_, DOUT_, H_, 2);
}